// round 1
// baseline (speedup 1.0000x reference)
#include <cuda_runtime.h>
#include <math.h>

// Problem-fixed maxima (buffers statically sized; runtime sizes derived from in_sizes)
#define NMAX   50000
#define EMAX   800000
#define ETMAX  (EMAX + NMAX)
#define GMAX   1024

// ---------------- scratch (no allocs allowed) ----------------
__device__ float g_h0 [NMAX * 64];      // relu(x@Wp+bp)
__device__ float g_xh1[NMAX * 128];     // h0@W1
__device__ float g_as1[NMAX * 4];
__device__ float g_ad1[NMAX * 4];
__device__ float g_max1[NMAX * 4];
__device__ float g_sum1[NMAX * 4];
__device__ float g_w1 [ETMAX * 4];
__device__ float g_out1[NMAX * 128];    // gat1 aggregate, then h1 (in place)
__device__ float g_xh2[NMAX * 64];
__device__ float g_as2[NMAX];
__device__ float g_ad2[NMAX];
__device__ float g_max2[NMAX];
__device__ float g_sum2[NMAX];
__device__ float g_w2 [ETMAX];
__device__ float g_out2[NMAX * 64];
__device__ float g_pool[GMAX * 64];
__device__ float g_cnt [GMAX];
__device__ int   g_is64;

// ---------------- helpers ----------------
__device__ __forceinline__ void atomicMaxF(float* addr, float v) {
    if (v >= 0.f) atomicMax((int*)addr, __float_as_int(v));
    else          atomicMin((unsigned int*)addr, __float_as_uint(v));
}

__device__ __forceinline__ int ld_idx(const void* p, long long i, int is64) {
    if (is64) return (int)((const long long*)p)[i];
    return ((const int*)p)[i];
}

__device__ __forceinline__ float warp_sum(float v) {
    #pragma unroll
    for (int o = 16; o > 0; o >>= 1) v += __shfl_down_sync(0xffffffffu, v, o);
    return v;
}

__device__ __forceinline__ float eluf(float v) { return v > 0.f ? v : expm1f(v); }

// ---------------- dtype detection (int64 vs int32 indices) ----------------
__global__ void k_detect(const void* ei) {
    const int* p = (const int*)ei;
    bool all0 = true;
    for (int i = threadIdx.x; i < 128; i += 32)
        if (p[2 * i + 1] != 0) all0 = false;
    all0 = __all_sync(0xffffffffu, all0);
    if (threadIdx.x == 0) g_is64 = all0 ? 1 : 0;
}

// ---------------- node projection: h0 = relu(x @ Wp + bp) ----------------
// x [n,128], Wp [128,64]
__global__ void k_nodeproj(const float* __restrict__ x, const float* __restrict__ Wp,
                           const float* __restrict__ bp, int n) {
    __shared__ float sW[128 * 64];   // 32 KB
    __shared__ float sx[16 * 128];   // 8 KB
    for (int i = threadIdx.x; i < 128 * 64; i += blockDim.x) sW[i] = Wp[i];
    int row0 = blockIdx.x * 16;
    for (int i = threadIdx.x; i < 16 * 128; i += blockDim.x) {
        int r = row0 + (i >> 7);
        sx[i] = (r < n) ? x[(long long)r * 128 + (i & 127)] : 0.f;
    }
    __syncthreads();
    int col = threadIdx.x & 63;
    int rl  = threadIdx.x >> 6;      // 0..3
    float bb = bp[col];
    for (int rr = rl; rr < 16; rr += 4) {
        int r = row0 + rr;
        if (r >= n) continue;
        float acc = bb;
        #pragma unroll 8
        for (int k = 0; k < 128; k++) acc += sx[rr * 128 + k] * sW[k * 64 + col];
        g_h0[(long long)r * 64 + col] = fmaxf(acc, 0.f);
    }
}

// ---------------- xh1 = h0 @ W1 ; a_s1/a_d1 per-head reductions ----------------
// W1 [64,128], as1/ad1 [4,32] flat = index c
__global__ void k_xh1(const float* __restrict__ W1, const float* __restrict__ as1,
                      const float* __restrict__ ad1, int n) {
    __shared__ float sW[64 * 128];   // 32 KB
    __shared__ float sh[32 * 64];    // 8 KB
    for (int i = threadIdx.x; i < 64 * 128; i += blockDim.x) sW[i] = W1[i];
    int row0 = blockIdx.x * 32;
    for (int i = threadIdx.x; i < 32 * 64; i += blockDim.x) {
        int r = row0 + (i >> 6);
        sh[i] = (r < n) ? g_h0[(long long)r * 64 + (i & 63)] : 0.f;
    }
    __syncthreads();
    int c = threadIdx.x;             // 0..127
    int h = c >> 5;
    float myas = as1[c], myad = ad1[c];
    for (int rr = 0; rr < 32; rr++) {
        int r = row0 + rr;
        if (r >= n) break;
        float acc = 0.f;
        #pragma unroll 8
        for (int k = 0; k < 64; k++) acc += sh[rr * 64 + k] * sW[k * 128 + c];
        g_xh1[(long long)r * 128 + c] = acc;
        float vs = warp_sum(acc * myas);
        float vd = warp_sum(acc * myad);
        if ((c & 31) == 0) {
            g_as1[r * 4 + h] = vs;
            g_ad1[r * 4 + h] = vd;
        }
    }
}

// ---------------- xh2 = h1 @ W2 ; a_s2/a_d2 ----------------
// h1 in g_out1 [n,128], W2 [128,64], as2/ad2 [64]
__global__ void k_xh2(const float* __restrict__ W2, const float* __restrict__ as2,
                      const float* __restrict__ ad2, int n) {
    __shared__ float sW[128 * 64];   // 32 KB
    __shared__ float sh[16 * 128];   // 8 KB
    __shared__ float rbuf[4];
    for (int i = threadIdx.x; i < 128 * 64; i += blockDim.x) sW[i] = W2[i];
    int row0 = blockIdx.x * 16;
    for (int i = threadIdx.x; i < 16 * 128; i += blockDim.x) {
        int r = row0 + (i >> 7);
        sh[i] = (r < n) ? g_out1[(long long)r * 128 + (i & 127)] : 0.f;
    }
    __syncthreads();
    int c = threadIdx.x;             // 0..63
    int w = c >> 5;
    float myas = as2[c], myad = ad2[c];
    for (int rr = 0; rr < 16; rr++) {
        int r = row0 + rr;
        if (r < n) {
            float acc = 0.f;
            #pragma unroll 8
            for (int k = 0; k < 128; k++) acc += sh[rr * 128 + k] * sW[k * 64 + c];
            g_xh2[(long long)r * 64 + c] = acc;
            float vs = warp_sum(acc * myas);
            float vd = warp_sum(acc * myad);
            if ((c & 31) == 0) { rbuf[w * 2 + 0] = vs; rbuf[w * 2 + 1] = vd; }
        }
        __syncthreads();
        if (r < n && c == 0) {
            g_as2[r] = rbuf[0] + rbuf[2];
            g_ad2[r] = rbuf[1] + rbuf[3];
        }
        __syncthreads();
    }
}

// ---------------- edge passes, GAT1 (H=4) ----------------
__global__ void k_edge_max1(const void* __restrict__ ei, int e, int et) {
    int idx = blockIdx.x * blockDim.x + threadIdx.x;
    if (idx >= et * 4) return;
    int edge = idx >> 2, h = idx & 3;
    int is64 = g_is64;
    int s, d;
    if (edge < e) { s = ld_idx(ei, edge, is64); d = ld_idx(ei, (long long)e + edge, is64); }
    else          { s = d = edge - e; }
    float ee = g_as1[s * 4 + h] + g_ad1[d * 4 + h];
    ee = ee > 0.f ? ee : 0.2f * ee;
    atomicMaxF(&g_max1[d * 4 + h], ee);
}

__global__ void k_edge_w1(const void* __restrict__ ei, int e, int et) {
    int idx = blockIdx.x * blockDim.x + threadIdx.x;
    if (idx >= et * 4) return;
    int edge = idx >> 2, h = idx & 3;
    int is64 = g_is64;
    int s, d;
    if (edge < e) { s = ld_idx(ei, edge, is64); d = ld_idx(ei, (long long)e + edge, is64); }
    else          { s = d = edge - e; }
    float ee = g_as1[s * 4 + h] + g_ad1[d * 4 + h];
    ee = ee > 0.f ? ee : 0.2f * ee;
    float w = __expf(ee - g_max1[d * 4 + h]);
    g_w1[idx] = w;
    atomicAdd(&g_sum1[d * 4 + h], w);
}

__global__ void k_scatter1(const void* __restrict__ ei, int e, int et) {
    unsigned idx = blockIdx.x * blockDim.x + threadIdx.x;
    if (idx >= (unsigned)et * 128u) return;
    int edge = idx >> 7;
    int c = idx & 127;
    int h = c >> 5;
    int is64 = g_is64;
    int s, d;
    if (edge < e) { s = ld_idx(ei, edge, is64); d = ld_idx(ei, (long long)e + edge, is64); }
    else          { s = d = edge - e; }
    float w = g_w1[(edge << 2) | h];
    atomicAdd(&g_out1[(long long)d * 128 + c], w * g_xh1[(long long)s * 128 + c]);
}

__global__ void k_finish1(const float* __restrict__ b1, int n) {
    int i = blockIdx.x * blockDim.x + threadIdx.x;
    if (i >= n * 128) return;
    int nn = i >> 7, c = i & 127, h = c >> 5;
    float v = g_out1[i] / (g_sum1[nn * 4 + h] + 1e-16f) + b1[c];
    g_out1[i] = eluf(v);
}

// ---------------- edge passes, GAT2 (H=1) ----------------
__global__ void k_edge_max2(const void* __restrict__ ei, int e, int et) {
    int edge = blockIdx.x * blockDim.x + threadIdx.x;
    if (edge >= et) return;
    int is64 = g_is64;
    int s, d;
    if (edge < e) { s = ld_idx(ei, edge, is64); d = ld_idx(ei, (long long)e + edge, is64); }
    else          { s = d = edge - e; }
    float ee = g_as2[s] + g_ad2[d];
    ee = ee > 0.f ? ee : 0.2f * ee;
    atomicMaxF(&g_max2[d], ee);
}

__global__ void k_edge_w2(const void* __restrict__ ei, int e, int et) {
    int edge = blockIdx.x * blockDim.x + threadIdx.x;
    if (edge >= et) return;
    int is64 = g_is64;
    int s, d;
    if (edge < e) { s = ld_idx(ei, edge, is64); d = ld_idx(ei, (long long)e + edge, is64); }
    else          { s = d = edge - e; }
    float ee = g_as2[s] + g_ad2[d];
    ee = ee > 0.f ? ee : 0.2f * ee;
    float w = __expf(ee - g_max2[d]);
    g_w2[edge] = w;
    atomicAdd(&g_sum2[d], w);
}

__global__ void k_scatter2(const void* __restrict__ ei, int e, int et) {
    unsigned idx = blockIdx.x * blockDim.x + threadIdx.x;
    if (idx >= (unsigned)et * 64u) return;
    int edge = idx >> 6;
    int c = idx & 63;
    int is64 = g_is64;
    int s, d;
    if (edge < e) { s = ld_idx(ei, edge, is64); d = ld_idx(ei, (long long)e + edge, is64); }
    else          { s = d = edge - e; }
    float w = g_w2[edge];
    atomicAdd(&g_out2[(long long)d * 64 + c], w * g_xh2[(long long)s * 64 + c]);
}

__global__ void k_finish2_pool(const float* __restrict__ b2, const void* __restrict__ batch, int n) {
    int i = blockIdx.x * blockDim.x + threadIdx.x;
    if (i >= n * 64) return;
    int nn = i >> 6, c = i & 63;
    float v = g_out2[i] / (g_sum2[nn] + 1e-16f) + b2[c];
    v = eluf(v);
    int b = ld_idx(batch, nn, g_is64);
    atomicAdd(&g_pool[b * 64 + c], v);
    if (c == 0) atomicAdd(&g_cnt[b], 1.0f);
}

// ---------------- graph-level MLP + heads ----------------
__global__ void k_mlp(const float* __restrict__ Wm1, const float* __restrict__ bm1,
                      const float* __restrict__ Wm2, const float* __restrict__ bm2,
                      const float* __restrict__ Wc,  const float* __restrict__ bc,
                      const float* __restrict__ Wr,  const float* __restrict__ br,
                      const float* __restrict__ Wv,  const float* __restrict__ bv,
                      float* __restrict__ out, int G) {
    int g = blockIdx.x;
    int c = threadIdx.x;   // 64 threads
    __shared__ float hg[64], z1[64], z2[64];
    __shared__ float part[6];
    float cnt = fmaxf(g_cnt[g], 1.f);
    hg[c] = g_pool[g * 64 + c] / cnt;
    __syncthreads();
    float acc = bm1[c];
    #pragma unroll 8
    for (int k = 0; k < 64; k++) acc += hg[k] * Wm1[k * 64 + c];
    z1[c] = fmaxf(acc, 0.f);
    __syncthreads();
    acc = bm2[c];
    #pragma unroll 8
    for (int k = 0; k < 64; k++) acc += z1[k] * Wm2[k * 64 + c];
    z2[c] = fmaxf(acc, 0.f);
    __syncthreads();
    float vc = warp_sum(z2[c] * Wc[c]);
    float vr = warp_sum(z2[c] * Wr[c]);
    float vv = warp_sum(z2[c] * Wv[c]);
    if ((c & 31) == 0) {
        int w = c >> 5;
        part[w * 3 + 0] = vc; part[w * 3 + 1] = vr; part[w * 3 + 2] = vv;
    }
    __syncthreads();
    if (c == 0) {
        float cl = part[0] + part[3] + bc[0];
        float rt = part[1] + part[4] + br[0];
        float vo = part[2] + part[5] + bv[0];
        out[g]         = cl;
        out[G + g]     = rt;
        out[2 * G + g] = fmaxf(vo, 0.f) + log1pf(expf(-fabsf(vo)));  // softplus
    }
}

// ---------------- launch ----------------
extern "C" void kernel_launch(void* const* d_in, const int* in_sizes, int n_in,
                              void* d_out, int out_size) {
    const float* x    = (const float*)d_in[0];
    const void*  ei   = d_in[1];
    const void*  batch= d_in[2];
    const float* Wp   = (const float*)d_in[3];
    const float* bp   = (const float*)d_in[4];
    const float* W1   = (const float*)d_in[5];
    const float* as1  = (const float*)d_in[6];
    const float* ad1  = (const float*)d_in[7];
    const float* b1   = (const float*)d_in[8];
    const float* W2   = (const float*)d_in[9];
    const float* as2  = (const float*)d_in[10];
    const float* ad2  = (const float*)d_in[11];
    const float* b2   = (const float*)d_in[12];
    const float* Wm1  = (const float*)d_in[13];
    const float* bm1  = (const float*)d_in[14];
    const float* Wm2  = (const float*)d_in[15];
    const float* bm2  = (const float*)d_in[16];
    const float* Wc   = (const float*)d_in[17];
    const float* bc   = (const float*)d_in[18];
    const float* Wr   = (const float*)d_in[19];
    const float* br   = (const float*)d_in[20];
    const float* Wv   = (const float*)d_in[21];
    const float* bv   = (const float*)d_in[22];
    float* out = (float*)d_out;

    int n  = in_sizes[0] / 128;
    int e  = in_sizes[1] / 2;
    int G  = out_size / 3;
    int et = e + n;

    void *p_max1, *p_sum1, *p_out1, *p_max2, *p_sum2, *p_out2, *p_pool, *p_cnt;
    cudaGetSymbolAddress(&p_max1, g_max1);
    cudaGetSymbolAddress(&p_sum1, g_sum1);
    cudaGetSymbolAddress(&p_out1, g_out1);
    cudaGetSymbolAddress(&p_max2, g_max2);
    cudaGetSymbolAddress(&p_sum2, g_sum2);
    cudaGetSymbolAddress(&p_out2, g_out2);
    cudaGetSymbolAddress(&p_pool, g_pool);
    cudaGetSymbolAddress(&p_cnt,  g_cnt);

    cudaMemsetAsync(p_max1, 0, (size_t)n * 4 * sizeof(float));
    cudaMemsetAsync(p_sum1, 0, (size_t)n * 4 * sizeof(float));
    cudaMemsetAsync(p_out1, 0, (size_t)n * 128 * sizeof(float));
    cudaMemsetAsync(p_max2, 0, (size_t)n * sizeof(float));
    cudaMemsetAsync(p_sum2, 0, (size_t)n * sizeof(float));
    cudaMemsetAsync(p_out2, 0, (size_t)n * 64 * sizeof(float));
    cudaMemsetAsync(p_pool, 0, (size_t)G * 64 * sizeof(float));
    cudaMemsetAsync(p_cnt,  0, (size_t)G * sizeof(float));

    k_detect<<<1, 32>>>(ei);
    k_nodeproj<<<(n + 15) / 16, 256>>>(x, Wp, bp, n);
    k_xh1<<<(n + 31) / 32, 128>>>(W1, as1, ad1, n);

    int t1 = et * 4;
    k_edge_max1<<<(t1 + 255) / 256, 256>>>(ei, e, et);
    k_edge_w1  <<<(t1 + 255) / 256, 256>>>(ei, e, et);
    unsigned ts1 = (unsigned)et * 128u;
    k_scatter1<<<(ts1 + 255u) / 256u, 256>>>(ei, e, et);
    k_finish1<<<(n * 128 + 255) / 256, 256>>>(b1, n);

    k_xh2<<<(n + 15) / 16, 64>>>(W2, as2, ad2, n);
    k_edge_max2<<<(et + 255) / 256, 256>>>(ei, e, et);
    k_edge_w2  <<<(et + 255) / 256, 256>>>(ei, e, et);
    unsigned ts2 = (unsigned)et * 64u;
    k_scatter2<<<(ts2 + 255u) / 256u, 256>>>(ei, e, et);
    k_finish2_pool<<<(n * 64 + 255) / 256, 256>>>(b2, batch, n);

    k_mlp<<<G, 64>>>(Wm1, bm1, Wm2, bm2, Wc, bc, Wr, br, Wv, bv, out, G);
}

// round 3
// speedup vs baseline: 2.3878x; 2.3878x over previous
#include <cuda_runtime.h>
#include <math.h>

#define NMAX   50000
#define EMAX   800000
#define ETMAX  (EMAX + NMAX)
#define GMAX   1024

// ---------------- scratch ----------------
__device__ __align__(16) float g_h0 [NMAX * 64];     // relu(x@Wp+bp)
__device__ __align__(16) float g_xh1[NMAX * 128];    // h0@W1
__device__ __align__(16) float g_out1[NMAX * 128];   // h1 = elu(gat1)
__device__ __align__(16) float g_xh2[NMAX * 64];     // h1@W2
__device__ float g_as1[NMAX * 4];
__device__ float g_ad1[NMAX * 4];
__device__ float g_as2[NMAX];
__device__ float g_ad2[NMAX];
__device__ float g_u1[64 * 8];    // [k][j] j<4: W1@as1 head j ; j>=4: W1@ad1
__device__ float g_u2[128 * 2];   // [k][j] j=0: W2@as2 ; j=1: W2@ad2
__device__ int   g_offs[NMAX + 1];
__device__ int   g_cursor[NMAX];
__device__ int   g_csrc[ETMAX];
__device__ float g_pool[GMAX * 64];
__device__ float g_cnt [GMAX];
__device__ int   g_is64;

// ---------------- helpers ----------------
__device__ __forceinline__ int ld_idx(const void* p, long long i, int is64) {
    if (is64) return (int)((const long long*)p)[i];
    return ((const int*)p)[i];
}
__device__ __forceinline__ float eluf(float v) { return v > 0.f ? v : expm1f(v); }
__device__ __forceinline__ float warp_sum(float v) {
    #pragma unroll
    for (int o = 16; o > 0; o >>= 1) v += __shfl_down_sync(0xffffffffu, v, o);
    return v;
}

// ---------------- dtype detection ----------------
__global__ void k_detect(const void* ei) {
    const int* p = (const int*)ei;
    bool all0 = true;
    for (int i = threadIdx.x; i < 128; i += 32)
        if (p[2 * i + 1] != 0) all0 = false;
    all0 = __all_sync(0xffffffffu, all0);
    if (threadIdx.x == 0) g_is64 = all0 ? 1 : 0;
}

// ---------------- CSR build ----------------
__global__ void k_hist(const void* __restrict__ ei, int e, int et) {
    int idx = blockIdx.x * blockDim.x + threadIdx.x;
    if (idx >= et) return;
    int is64 = g_is64;
    int d = (idx < e) ? ld_idx(ei, (long long)e + idx, is64) : (idx - e);
    atomicAdd(&g_offs[d + 1], 1);
}

__global__ void k_scan(int n1) {   // inclusive scan of g_offs[0..n1)
    __shared__ int part[1024];
    int t = threadIdx.x;
    int chunk = (n1 + 1023) >> 10;
    int beg = t * chunk;
    int end = beg + chunk; if (end > n1) end = n1;
    int s = 0;
    for (int i = beg; i < end; i++) s += g_offs[i];
    part[t] = s;
    __syncthreads();
    for (int off = 1; off < 1024; off <<= 1) {
        int v = (t >= off) ? part[t - off] : 0;
        __syncthreads();
        part[t] += v;
        __syncthreads();
    }
    int run = (t == 0) ? 0 : part[t - 1];
    for (int i = beg; i < end; i++) { run += g_offs[i]; g_offs[i] = run; }
}

__global__ void k_place(const void* __restrict__ ei, int e, int et) {
    int idx = blockIdx.x * blockDim.x + threadIdx.x;
    if (idx >= et) return;
    int is64 = g_is64;
    int s, d;
    if (idx < e) { s = ld_idx(ei, idx, is64); d = ld_idx(ei, (long long)e + idx, is64); }
    else         { s = d = idx - e; }
    int pos = atomicAdd(&g_cursor[d], 1);
    g_csrc[pos] = s;
}

// ---------------- u = W @ att  precompute ----------------
__global__ void k_uprep(const float* __restrict__ W1, const float* __restrict__ as1,
                        const float* __restrict__ ad1, const float* __restrict__ W2,
                        const float* __restrict__ as2, const float* __restrict__ ad2) {
    int t = threadIdx.x;
    for (int i = t; i < 64 * 8; i += blockDim.x) {
        int k = i >> 3, j = i & 7, h = j & 3;
        const float* av = (j < 4) ? as1 : ad1;
        float s = 0.f;
        for (int c = 0; c < 32; c++) s += W1[k * 128 + h * 32 + c] * av[h * 32 + c];
        g_u1[i] = s;
    }
    for (int i = t; i < 128 * 2; i += blockDim.x) {
        int k = i >> 1, j = i & 1;
        const float* av = j ? ad2 : as2;
        float s = 0.f;
        for (int c = 0; c < 64; c++) s += W2[k * 64 + c] * av[c];
        g_u2[i] = s;
    }
}

// ---------------- GEMM K=128 -> M=64 (nodeproj w/ relu, xh2) ----------------
__global__ void k_gemm_k128_m64(const float* __restrict__ A, const float* __restrict__ W,
                                const float* __restrict__ bias, float* __restrict__ out,
                                int n, int relu) {
    __shared__ float sW[128 * 64];   // 32 KB
    __shared__ float sA[32 * 128];   // 16 KB
    int t = threadIdx.x;             // 128
    for (int i = t; i < 128 * 64; i += 128) sW[i] = W[i];
    int row0 = blockIdx.x * 32;
    for (int i = t; i < 32 * 128; i += 128) {
        int r = row0 + (i >> 7);
        sA[i] = (r < n) ? A[(size_t)r * 128 + (i & 127)] : 0.f;
    }
    __syncthreads();
    int lane = t & 31, wid = t >> 5;
    int r0 = wid * 8;
    float2 acc[8];
    #pragma unroll
    for (int r = 0; r < 8; r++) acc[r] = make_float2(0.f, 0.f);
    #pragma unroll 4
    for (int k = 0; k < 128; k++) {
        float2 w = *(const float2*)&sW[k * 64 + lane * 2];
        #pragma unroll
        for (int r = 0; r < 8; r++) {
            float a = sA[(r0 + r) * 128 + k];
            acc[r].x += a * w.x; acc[r].y += a * w.y;
        }
    }
    float bx = bias ? bias[lane * 2] : 0.f;
    float by = bias ? bias[lane * 2 + 1] : 0.f;
    #pragma unroll
    for (int r = 0; r < 8; r++) {
        int row = row0 + r0 + r;
        if (row < n) {
            float2 o = acc[r];
            o.x += bx; o.y += by;
            if (relu) { o.x = fmaxf(o.x, 0.f); o.y = fmaxf(o.y, 0.f); }
            *(float2*)&out[(size_t)row * 64 + lane * 2] = o;
        }
    }
}

// ---------------- GEMM K=64 -> M=128 (xh1) ----------------
__global__ void k_gemm_k64_m128(const float* __restrict__ A, const float* __restrict__ W,
                                float* __restrict__ out, int n) {
    __shared__ float sW[64 * 128];   // 32 KB
    __shared__ float sA[32 * 64];    // 8 KB
    int t = threadIdx.x;             // 128
    for (int i = t; i < 64 * 128; i += 128) sW[i] = W[i];
    int row0 = blockIdx.x * 32;
    for (int i = t; i < 32 * 64; i += 128) {
        int r = row0 + (i >> 6);
        sA[i] = (r < n) ? A[(size_t)r * 64 + (i & 63)] : 0.f;
    }
    __syncthreads();
    int lane = t & 31, wid = t >> 5;
    int r0 = wid * 8;
    float4 acc[8];
    #pragma unroll
    for (int r = 0; r < 8; r++) acc[r] = make_float4(0.f, 0.f, 0.f, 0.f);
    #pragma unroll 2
    for (int k = 0; k < 64; k++) {
        float4 w = *(const float4*)&sW[k * 128 + lane * 4];
        #pragma unroll
        for (int r = 0; r < 8; r++) {
            float a = sA[(r0 + r) * 64 + k];
            acc[r].x += a * w.x; acc[r].y += a * w.y;
            acc[r].z += a * w.z; acc[r].w += a * w.w;
        }
    }
    #pragma unroll
    for (int r = 0; r < 8; r++) {
        int row = row0 + r0 + r;
        if (row < n)
            *(float4*)&out[(size_t)row * 128 + lane * 4] = acc[r];
    }
}

// ---------------- attention coefficients from features ----------------
__global__ void k_att1(int n) {  // h0 [n,64] @ u1 [64,8] -> as1/ad1
    int node = blockIdx.x * 8 + (threadIdx.x >> 5);
    if (node >= n) return;
    int lane = threadIdx.x & 31;
    float acc[8] = {0.f, 0.f, 0.f, 0.f, 0.f, 0.f, 0.f, 0.f};
    for (int k = lane; k < 64; k += 32) {
        float f = g_h0[(size_t)node * 64 + k];
        #pragma unroll
        for (int j = 0; j < 8; j++) acc[j] += f * g_u1[k * 8 + j];
    }
    #pragma unroll
    for (int j = 0; j < 8; j++) acc[j] = warp_sum(acc[j]);
    if (lane == 0) {
        #pragma unroll
        for (int h = 0; h < 4; h++) {
            g_as1[node * 4 + h] = acc[h];
            g_ad1[node * 4 + h] = acc[4 + h];
        }
    }
}

__global__ void k_att2(int n) {  // h1 [n,128] @ u2 [128,2] -> as2/ad2
    int node = blockIdx.x * 8 + (threadIdx.x >> 5);
    if (node >= n) return;
    int lane = threadIdx.x & 31;
    float a0 = 0.f, a1 = 0.f;
    for (int k = lane; k < 128; k += 32) {
        float f = g_out1[(size_t)node * 128 + k];
        a0 += f * g_u2[k * 2];
        a1 += f * g_u2[k * 2 + 1];
    }
    a0 = warp_sum(a0); a1 = warp_sum(a1);
    if (lane == 0) { g_as2[node] = a0; g_ad2[node] = a1; }
}

// ---------------- GAT1 aggregation: warp per dst node ----------------
__global__ void k_agg1(const float* __restrict__ b1, int n) {
    int node = blockIdx.x * 8 + (threadIdx.x >> 5);
    if (node >= n) return;
    int lane = threadIdx.x & 31;
    int h = lane >> 3;                     // 4 channels (float4) per lane, all same head
    float ad = g_ad1[node * 4 + h];
    int beg = g_offs[node], end = g_offs[node + 1];
    const float4* xh4 = (const float4*)g_xh1;
    float4 acc = make_float4(0.f, 0.f, 0.f, 0.f);
    float wsum = 0.f;
    for (int j = beg; j < end; j++) {
        int s = g_csrc[j];
        float e = g_as1[s * 4 + h] + ad;
        e = e > 0.f ? e : 0.2f * e;
        float w = __expf(e);
        float4 v = xh4[(size_t)s * 32 + lane];
        acc.x += w * v.x; acc.y += w * v.y; acc.z += w * v.z; acc.w += w * v.w;
        wsum += w;
    }
    float inv = 1.f / (wsum + 1e-16f);
    float4 bb = ((const float4*)b1)[lane];
    float4 o;
    o.x = eluf(acc.x * inv + bb.x);
    o.y = eluf(acc.y * inv + bb.y);
    o.z = eluf(acc.z * inv + bb.z);
    o.w = eluf(acc.w * inv + bb.w);
    ((float4*)g_out1)[(size_t)node * 32 + lane] = o;
}

// ---------------- GAT2 aggregation + elu + mean-pool scatter ----------------
__global__ void k_agg2(const float* __restrict__ b2, const void* __restrict__ batch, int n) {
    int node = blockIdx.x * 8 + (threadIdx.x >> 5);
    if (node >= n) return;
    int lane = threadIdx.x & 31;
    float ad = g_ad2[node];
    int beg = g_offs[node], end = g_offs[node + 1];
    const float2* xh2 = (const float2*)g_xh2;
    float2 acc = make_float2(0.f, 0.f);
    float wsum = 0.f;
    for (int j = beg; j < end; j++) {
        int s = g_csrc[j];
        float e = g_as2[s] + ad;
        e = e > 0.f ? e : 0.2f * e;
        float w = __expf(e);
        float2 v = xh2[(size_t)s * 32 + lane];
        acc.x += w * v.x; acc.y += w * v.y;
        wsum += w;
    }
    float inv = 1.f / (wsum + 1e-16f);
    float2 bb = ((const float2*)b2)[lane];
    float ox = eluf(acc.x * inv + bb.x);
    float oy = eluf(acc.y * inv + bb.y);
    int b = ld_idx(batch, node, g_is64);
    atomicAdd(&g_pool[b * 64 + lane * 2], ox);
    atomicAdd(&g_pool[b * 64 + lane * 2 + 1], oy);
    if (lane == 0) atomicAdd(&g_cnt[b], 1.0f);
}

// ---------------- graph-level MLP + heads ----------------
__global__ void k_mlp(const float* __restrict__ Wm1, const float* __restrict__ bm1,
                      const float* __restrict__ Wm2, const float* __restrict__ bm2,
                      const float* __restrict__ Wc,  const float* __restrict__ bc,
                      const float* __restrict__ Wr,  const float* __restrict__ br,
                      const float* __restrict__ Wv,  const float* __restrict__ bv,
                      float* __restrict__ out, int G) {
    int g = blockIdx.x;
    int c = threadIdx.x;   // 64 threads
    __shared__ float hg[64], z1[64], z2[64];
    __shared__ float part[6];
    float cnt = fmaxf(g_cnt[g], 1.f);
    hg[c] = g_pool[g * 64 + c] / cnt;
    __syncthreads();
    float acc = bm1[c];
    #pragma unroll 8
    for (int k = 0; k < 64; k++) acc += hg[k] * Wm1[k * 64 + c];
    z1[c] = fmaxf(acc, 0.f);
    __syncthreads();
    acc = bm2[c];
    #pragma unroll 8
    for (int k = 0; k < 64; k++) acc += z1[k] * Wm2[k * 64 + c];
    z2[c] = fmaxf(acc, 0.f);
    __syncthreads();
    float vc = warp_sum(z2[c] * Wc[c]);
    float vr = warp_sum(z2[c] * Wr[c]);
    float vv = warp_sum(z2[c] * Wv[c]);
    if ((c & 31) == 0) {
        int w = c >> 5;
        part[w * 3 + 0] = vc; part[w * 3 + 1] = vr; part[w * 3 + 2] = vv;
    }
    __syncthreads();
    if (c == 0) {
        float cl = part[0] + part[3] + bc[0];
        float rt = part[1] + part[4] + br[0];
        float vo = part[2] + part[5] + bv[0];
        out[g]         = cl;
        out[G + g]     = rt;
        out[2 * G + g] = fmaxf(vo, 0.f) + log1pf(expf(-fabsf(vo)));  // softplus
    }
}

// ---------------- launch ----------------
extern "C" void kernel_launch(void* const* d_in, const int* in_sizes, int n_in,
                              void* d_out, int out_size) {
    const float* x    = (const float*)d_in[0];
    const void*  ei   = d_in[1];
    const void*  batch= d_in[2];
    const float* Wp   = (const float*)d_in[3];
    const float* bp   = (const float*)d_in[4];
    const float* W1   = (const float*)d_in[5];
    const float* as1  = (const float*)d_in[6];
    const float* ad1  = (const float*)d_in[7];
    const float* b1   = (const float*)d_in[8];
    const float* W2   = (const float*)d_in[9];
    const float* as2  = (const float*)d_in[10];
    const float* ad2  = (const float*)d_in[11];
    const float* b2   = (const float*)d_in[12];
    const float* Wm1  = (const float*)d_in[13];
    const float* bm1  = (const float*)d_in[14];
    const float* Wm2  = (const float*)d_in[15];
    const float* bm2  = (const float*)d_in[16];
    const float* Wc   = (const float*)d_in[17];
    const float* bc   = (const float*)d_in[18];
    const float* Wr   = (const float*)d_in[19];
    const float* br   = (const float*)d_in[20];
    const float* Wv   = (const float*)d_in[21];
    const float* bv   = (const float*)d_in[22];
    float* out = (float*)d_out;

    int n  = in_sizes[0] / 128;
    int e  = in_sizes[1] / 2;
    int G  = out_size / 3;
    int et = e + n;

    // REAL device addresses of __device__ globals (host-side symbol names are
    // host shadow addresses — passing them to kernels is UB; on GB300/ATS the
    // GPU would silently dereference host memory).
    void *p_offs, *p_cursor, *p_pool, *p_cnt;
    void *p_h0, *p_xh1, *p_out1, *p_xh2;
    cudaGetSymbolAddress(&p_offs,   g_offs);
    cudaGetSymbolAddress(&p_cursor, g_cursor);
    cudaGetSymbolAddress(&p_pool,   g_pool);
    cudaGetSymbolAddress(&p_cnt,    g_cnt);
    cudaGetSymbolAddress(&p_h0,     g_h0);
    cudaGetSymbolAddress(&p_xh1,    g_xh1);
    cudaGetSymbolAddress(&p_out1,   g_out1);
    cudaGetSymbolAddress(&p_xh2,    g_xh2);
    float* d_h0   = (float*)p_h0;
    float* d_xh1  = (float*)p_xh1;
    float* d_out1 = (float*)p_out1;
    float* d_xh2  = (float*)p_xh2;

    cudaMemsetAsync(p_offs, 0, (size_t)(n + 1) * sizeof(int));
    cudaMemsetAsync(p_pool, 0, (size_t)G * 64 * sizeof(float));
    cudaMemsetAsync(p_cnt,  0, (size_t)G * sizeof(float));

    k_detect<<<1, 32>>>(ei);

    // CSR build (shared by both GAT layers)
    k_hist<<<(et + 255) / 256, 256>>>(ei, e, et);
    k_scan<<<1, 1024>>>(n + 1);
    cudaMemcpyAsync(p_cursor, p_offs, (size_t)n * sizeof(int), cudaMemcpyDeviceToDevice);
    k_place<<<(et + 255) / 256, 256>>>(ei, e, et);

    k_uprep<<<1, 256>>>(W1, as1, ad1, W2, as2, ad2);

    // node projection: h0 = relu(x @ Wp + bp)
    k_gemm_k128_m64<<<(n + 31) / 32, 128>>>(x, Wp, bp, d_h0, n, 1);
    // layer-1 attention coefficients + features
    k_att1<<<(n + 7) / 8, 256>>>(n);
    k_gemm_k64_m128<<<(n + 31) / 32, 128>>>(d_h0, W1, d_xh1, n);
    // layer-1 aggregation -> h1 (elu fused)
    k_agg1<<<(n + 7) / 8, 256>>>(b1, n);

    // layer-2
    k_att2<<<(n + 7) / 8, 256>>>(n);
    k_gemm_k128_m64<<<(n + 31) / 32, 128>>>(d_out1, W2, (const float*)nullptr, d_xh2, n, 0);
    k_agg2<<<(n + 7) / 8, 256>>>(b2, batch, n);

    k_mlp<<<G, 64>>>(Wm1, bm1, Wm2, bm2, Wc, bc, Wr, br, Wv, bv, out, G);
}

// round 4
// speedup vs baseline: 2.5059x; 1.0495x over previous
#include <cuda_runtime.h>
#include <math.h>

#define NMAX   50000
#define EMAX   800000
#define ETMAX  (EMAX + NMAX)
#define GMAX   1024

// ---------------- scratch ----------------
__device__ __align__(16) float g_h0 [NMAX * 64];     // relu(x@Wp+bp)
__device__ __align__(16) float g_xh1[NMAX * 128];    // h0@W1
__device__ __align__(16) float g_out1[NMAX * 128];   // h1 = elu(gat1)
__device__ __align__(16) float g_xh2[NMAX * 64];     // h1@W2
__device__ float g_as1[NMAX * 4];
__device__ float g_ad1[NMAX * 4];
__device__ float g_as2[NMAX];
__device__ float g_ad2[NMAX];
__device__ int   g_offs[NMAX + 1];
__device__ int   g_cursor[NMAX + 1];
__device__ int   g_csrc[ETMAX];
__device__ float g_pool[GMAX * 64];
__device__ float g_cnt [GMAX];
__device__ int   g_is64;

// ---------------- helpers ----------------
__device__ __forceinline__ int ld_idx(const void* p, long long i, int is64) {
    if (is64) return (int)((const long long*)p)[i];
    return ((const int*)p)[i];
}
__device__ __forceinline__ float eluf(float v) { return v > 0.f ? v : expm1f(v); }
__device__ __forceinline__ float warp_sum(float v) {
    #pragma unroll
    for (int o = 16; o > 0; o >>= 1) v += __shfl_down_sync(0xffffffffu, v, o);
    return v;
}

// ---------------- dtype detection ----------------
__global__ void k_detect(const void* ei) {
    const int* p = (const int*)ei;
    bool all0 = true;
    for (int i = threadIdx.x; i < 128; i += 32)
        if (p[2 * i + 1] != 0) all0 = false;
    all0 = __all_sync(0xffffffffu, all0);
    if (threadIdx.x == 0) g_is64 = all0 ? 1 : 0;
}

// ---------------- CSR build (4 edges / thread) ----------------
__global__ void k_hist(const void* __restrict__ ei, int e, int et) {
    int base = (blockIdx.x * blockDim.x + threadIdx.x) * 4;
    if (base >= et) return;
    int is64 = g_is64;
    #pragma unroll
    for (int u = 0; u < 4; u++) {
        int idx = base + u;
        if (idx >= et) break;
        int d = (idx < e) ? ld_idx(ei, (long long)e + idx, is64) : (idx - e);
        atomicAdd(&g_offs[d + 1], 1);
    }
}

__global__ void k_scan(int n1) {   // inclusive scan of g_offs[0..n1); also fills cursor
    __shared__ int part[1024];
    int t = threadIdx.x;
    int chunk = (n1 + 1023) >> 10;
    int beg = t * chunk;
    int end = beg + chunk; if (end > n1) end = n1;
    int s = 0;
    for (int i = beg; i < end; i++) s += g_offs[i];
    part[t] = s;
    __syncthreads();
    for (int off = 1; off < 1024; off <<= 1) {
        int v = (t >= off) ? part[t - off] : 0;
        __syncthreads();
        part[t] += v;
        __syncthreads();
    }
    int run = (t == 0) ? 0 : part[t - 1];
    for (int i = beg; i < end; i++) {
        run += g_offs[i];
        g_offs[i] = run;
        g_cursor[i] = run;   // cursor[node] = start offset
    }
}

__global__ void k_place(const void* __restrict__ ei, int e, int et) {
    int base = (blockIdx.x * blockDim.x + threadIdx.x) * 4;
    if (base >= et) return;
    int is64 = g_is64;
    #pragma unroll
    for (int u = 0; u < 4; u++) {
        int idx = base + u;
        if (idx >= et) break;
        int s, d;
        if (idx < e) { s = ld_idx(ei, idx, is64); d = ld_idx(ei, (long long)e + idx, is64); }
        else         { s = d = idx - e; }
        int pos = atomicAdd(&g_cursor[d], 1);
        g_csrc[pos] = s;
    }
}

// ============ GEMM A[n,128] @ W[128,64] -> out[n,64] ============
// mode 0: += bias, relu (node projection)
// mode 1: no bias, write g_as2/g_ad2 = out @ as2 / out @ ad2 (xh2 + att2)
// dynamic smem: sW[128*64] + sAt[128*36]
__global__ void k_gemm_k128_m64(const float* __restrict__ A, const float* __restrict__ W,
                                const float* __restrict__ bias,
                                const float* __restrict__ av_s, const float* __restrict__ av_d,
                                float* __restrict__ out, int n, int mode) {
    extern __shared__ float sm[];
    float* sW  = sm;              // [128][64]
    float* sAt = sm + 128 * 64;   // [k][r] stride 36
    int t = threadIdx.x;          // 128
    for (int i = t; i < 128 * 64; i += 128) sW[i] = W[i];
    int row0 = blockIdx.x * 32;
    for (int i = t; i < 32 * 128; i += 128) {
        int r = i >> 7, k = i & 127;
        float v = (row0 + r < n) ? A[(size_t)(row0 + r) * 128 + k] : 0.f;
        sAt[k * 36 + r] = v;
    }
    __syncthreads();
    int cg = t & 15, rg = t >> 4;
    int c0 = cg * 4, r0 = rg * 4;
    float4 acc0 = make_float4(0.f,0.f,0.f,0.f), acc1 = acc0, acc2 = acc0, acc3 = acc0;
    #pragma unroll 4
    for (int k = 0; k < 128; k++) {
        float4 a4 = *(const float4*)&sAt[k * 36 + r0];
        float4 w4 = *(const float4*)&sW [k * 64 + c0];
        acc0.x += a4.x*w4.x; acc0.y += a4.x*w4.y; acc0.z += a4.x*w4.z; acc0.w += a4.x*w4.w;
        acc1.x += a4.y*w4.x; acc1.y += a4.y*w4.y; acc1.z += a4.y*w4.z; acc1.w += a4.y*w4.w;
        acc2.x += a4.z*w4.x; acc2.y += a4.z*w4.y; acc2.z += a4.z*w4.z; acc2.w += a4.z*w4.w;
        acc3.x += a4.w*w4.x; acc3.y += a4.w*w4.y; acc3.z += a4.w*w4.z; acc3.w += a4.w*w4.w;
    }
    float4 accs[4] = {acc0, acc1, acc2, acc3};
    if (mode == 0) {
        float4 bb;
        bb.x = bias[c0]; bb.y = bias[c0+1]; bb.z = bias[c0+2]; bb.w = bias[c0+3];
        #pragma unroll
        for (int j = 0; j < 4; j++) {
            int row = row0 + r0 + j;
            if (row < n) {
                float4 o = accs[j];
                o.x = fmaxf(o.x + bb.x, 0.f); o.y = fmaxf(o.y + bb.y, 0.f);
                o.z = fmaxf(o.z + bb.z, 0.f); o.w = fmaxf(o.w + bb.w, 0.f);
                *(float4*)&out[(size_t)row * 64 + c0] = o;
            }
        }
    } else {
        float4 sv, dv;
        sv.x = av_s[c0]; sv.y = av_s[c0+1]; sv.z = av_s[c0+2]; sv.w = av_s[c0+3];
        dv.x = av_d[c0]; dv.y = av_d[c0+1]; dv.z = av_d[c0+2]; dv.w = av_d[c0+3];
        #pragma unroll
        for (int j = 0; j < 4; j++) {
            int row = row0 + r0 + j;
            float4 o = accs[j];
            float ps = o.x*sv.x + o.y*sv.y + o.z*sv.z + o.w*sv.w;
            float pd = o.x*dv.x + o.y*dv.y + o.z*dv.z + o.w*dv.w;
            #pragma unroll
            for (int off = 1; off < 16; off <<= 1) {
                ps += __shfl_xor_sync(0xffffffffu, ps, off);
                pd += __shfl_xor_sync(0xffffffffu, pd, off);
            }
            if (row < n) {
                *(float4*)&out[(size_t)row * 64 + c0] = o;
                if (cg == 0) { g_as2[row] = ps; g_ad2[row] = pd; }
            }
        }
    }
}

// ============ GEMM A[n,64] @ W1[64,128] -> g_xh1[n,128], + att1 ============
// static smem: sW[64*128] (32KB) + sAt[64*36] (9KB)
__global__ void k_gemm_k64_m128(const float* __restrict__ A, const float* __restrict__ W,
                                const float* __restrict__ av_s, const float* __restrict__ av_d,
                                float* __restrict__ out, int n) {
    __shared__ float sW[64 * 128];
    __shared__ float sAt[64 * 36];
    int t = threadIdx.x;          // 128
    for (int i = t; i < 64 * 128; i += 128) sW[i] = W[i];
    int row0 = blockIdx.x * 32;
    for (int i = t; i < 32 * 64; i += 128) {
        int r = i >> 6, k = i & 63;
        float v = (row0 + r < n) ? A[(size_t)(row0 + r) * 64 + k] : 0.f;
        sAt[k * 36 + r] = v;
    }
    __syncthreads();
    int cg = t & 15, rg = t >> 4;
    int c0 = cg * 8, r0 = rg * 4;
    float4 aA0 = make_float4(0.f,0.f,0.f,0.f), aA1 = aA0, aA2 = aA0, aA3 = aA0;
    float4 aB0 = aA0, aB1 = aA0, aB2 = aA0, aB3 = aA0;
    #pragma unroll 4
    for (int k = 0; k < 64; k++) {
        float4 a4 = *(const float4*)&sAt[k * 36 + r0];
        float4 wa = *(const float4*)&sW [k * 128 + c0];
        float4 wb = *(const float4*)&sW [k * 128 + c0 + 4];
        aA0.x += a4.x*wa.x; aA0.y += a4.x*wa.y; aA0.z += a4.x*wa.z; aA0.w += a4.x*wa.w;
        aA1.x += a4.y*wa.x; aA1.y += a4.y*wa.y; aA1.z += a4.y*wa.z; aA1.w += a4.y*wa.w;
        aA2.x += a4.z*wa.x; aA2.y += a4.z*wa.y; aA2.z += a4.z*wa.z; aA2.w += a4.z*wa.w;
        aA3.x += a4.w*wa.x; aA3.y += a4.w*wa.y; aA3.z += a4.w*wa.z; aA3.w += a4.w*wa.w;
        aB0.x += a4.x*wb.x; aB0.y += a4.x*wb.y; aB0.z += a4.x*wb.z; aB0.w += a4.x*wb.w;
        aB1.x += a4.y*wb.x; aB1.y += a4.y*wb.y; aB1.z += a4.y*wb.z; aB1.w += a4.y*wb.w;
        aB2.x += a4.z*wb.x; aB2.y += a4.z*wb.y; aB2.z += a4.z*wb.z; aB2.w += a4.z*wb.w;
        aB3.x += a4.w*wb.x; aB3.y += a4.w*wb.y; aB3.z += a4.w*wb.z; aB3.w += a4.w*wb.w;
    }
    float4 A_[4] = {aA0, aA1, aA2, aA3};
    float4 B_[4] = {aB0, aB1, aB2, aB3};
    int head = cg >> 2;                  // c0/32
    float4 s0, s1, d0, d1;
    s0.x=av_s[c0];   s0.y=av_s[c0+1]; s0.z=av_s[c0+2]; s0.w=av_s[c0+3];
    s1.x=av_s[c0+4]; s1.y=av_s[c0+5]; s1.z=av_s[c0+6]; s1.w=av_s[c0+7];
    d0.x=av_d[c0];   d0.y=av_d[c0+1]; d0.z=av_d[c0+2]; d0.w=av_d[c0+3];
    d1.x=av_d[c0+4]; d1.y=av_d[c0+5]; d1.z=av_d[c0+6]; d1.w=av_d[c0+7];
    #pragma unroll
    for (int j = 0; j < 4; j++) {
        int row = row0 + r0 + j;
        float4 oa = A_[j], ob = B_[j];
        float ps = oa.x*s0.x + oa.y*s0.y + oa.z*s0.z + oa.w*s0.w
                 + ob.x*s1.x + ob.y*s1.y + ob.z*s1.z + ob.w*s1.w;
        float pd = oa.x*d0.x + oa.y*d0.y + oa.z*d0.z + oa.w*d0.w
                 + ob.x*d1.x + ob.y*d1.y + ob.z*d1.z + ob.w*d1.w;
        ps += __shfl_xor_sync(0xffffffffu, ps, 1);
        ps += __shfl_xor_sync(0xffffffffu, ps, 2);
        pd += __shfl_xor_sync(0xffffffffu, pd, 1);
        pd += __shfl_xor_sync(0xffffffffu, pd, 2);
        if (row < n) {
            *(float4*)&out[(size_t)row * 128 + c0]     = oa;
            *(float4*)&out[(size_t)row * 128 + c0 + 4] = ob;
            if ((cg & 3) == 0) {
                g_as1[row * 4 + head] = ps;
                g_ad1[row * 4 + head] = pd;
            }
        }
    }
}

// ---------------- GAT1 aggregation: warp per dst node ----------------
__global__ void k_agg1(const float* __restrict__ b1, int n) {
    int node = blockIdx.x * 8 + (threadIdx.x >> 5);
    if (node >= n) return;
    int lane = threadIdx.x & 31;
    int h = lane >> 3;
    float ad = g_ad1[node * 4 + h];
    int beg = g_offs[node], end = g_offs[node + 1];
    const float4* xh4 = (const float4*)g_xh1;
    float4 accA = make_float4(0.f,0.f,0.f,0.f), accB = accA;
    float wsA = 0.f, wsB = 0.f;
    int j = beg;
    for (; j + 1 < end; j += 2) {
        int s0 = g_csrc[j], s1 = g_csrc[j + 1];
        float e0 = g_as1[s0 * 4 + h] + ad;
        float e1 = g_as1[s1 * 4 + h] + ad;
        e0 = e0 > 0.f ? e0 : 0.2f * e0;
        e1 = e1 > 0.f ? e1 : 0.2f * e1;
        float w0 = __expf(e0), w1 = __expf(e1);
        float4 v0 = xh4[(size_t)s0 * 32 + lane];
        float4 v1 = xh4[(size_t)s1 * 32 + lane];
        accA.x += w0*v0.x; accA.y += w0*v0.y; accA.z += w0*v0.z; accA.w += w0*v0.w;
        accB.x += w1*v1.x; accB.y += w1*v1.y; accB.z += w1*v1.z; accB.w += w1*v1.w;
        wsA += w0; wsB += w1;
    }
    if (j < end) {
        int s0 = g_csrc[j];
        float e0 = g_as1[s0 * 4 + h] + ad;
        e0 = e0 > 0.f ? e0 : 0.2f * e0;
        float w0 = __expf(e0);
        float4 v0 = xh4[(size_t)s0 * 32 + lane];
        accA.x += w0*v0.x; accA.y += w0*v0.y; accA.z += w0*v0.z; accA.w += w0*v0.w;
        wsA += w0;
    }
    float inv = 1.f / (wsA + wsB + 1e-16f);
    float4 bb = ((const float4*)b1)[lane];
    float4 o;
    o.x = eluf((accA.x + accB.x) * inv + bb.x);
    o.y = eluf((accA.y + accB.y) * inv + bb.y);
    o.z = eluf((accA.z + accB.z) * inv + bb.z);
    o.w = eluf((accA.w + accB.w) * inv + bb.w);
    ((float4*)g_out1)[(size_t)node * 32 + lane] = o;
}

// ---------------- GAT2 aggregation + elu + mean-pool scatter ----------------
__global__ void k_agg2(const float* __restrict__ b2, const void* __restrict__ batch, int n) {
    int node = blockIdx.x * 8 + (threadIdx.x >> 5);
    if (node >= n) return;
    int lane = threadIdx.x & 31;
    float ad = g_ad2[node];
    int beg = g_offs[node], end = g_offs[node + 1];
    const float2* xh2 = (const float2*)g_xh2;
    float2 accA = make_float2(0.f,0.f), accB = accA;
    float wsA = 0.f, wsB = 0.f;
    int j = beg;
    for (; j + 1 < end; j += 2) {
        int s0 = g_csrc[j], s1 = g_csrc[j + 1];
        float e0 = g_as2[s0] + ad;
        float e1 = g_as2[s1] + ad;
        e0 = e0 > 0.f ? e0 : 0.2f * e0;
        e1 = e1 > 0.f ? e1 : 0.2f * e1;
        float w0 = __expf(e0), w1 = __expf(e1);
        float2 v0 = xh2[(size_t)s0 * 32 + lane];
        float2 v1 = xh2[(size_t)s1 * 32 + lane];
        accA.x += w0*v0.x; accA.y += w0*v0.y;
        accB.x += w1*v1.x; accB.y += w1*v1.y;
        wsA += w0; wsB += w1;
    }
    if (j < end) {
        int s0 = g_csrc[j];
        float e0 = g_as2[s0] + ad;
        e0 = e0 > 0.f ? e0 : 0.2f * e0;
        float w0 = __expf(e0);
        float2 v0 = xh2[(size_t)s0 * 32 + lane];
        accA.x += w0*v0.x; accA.y += w0*v0.y;
        wsA += w0;
    }
    float inv = 1.f / (wsA + wsB + 1e-16f);
    float2 bb = ((const float2*)b2)[lane];
    float ox = eluf((accA.x + accB.x) * inv + bb.x);
    float oy = eluf((accA.y + accB.y) * inv + bb.y);
    int b = ld_idx(batch, node, g_is64);
    atomicAdd(&g_pool[b * 64 + lane * 2], ox);
    atomicAdd(&g_pool[b * 64 + lane * 2 + 1], oy);
    if (lane == 0) atomicAdd(&g_cnt[b], 1.0f);
}

// ---------------- graph-level MLP + heads ----------------
__global__ void k_mlp(const float* __restrict__ Wm1, const float* __restrict__ bm1,
                      const float* __restrict__ Wm2, const float* __restrict__ bm2,
                      const float* __restrict__ Wc,  const float* __restrict__ bc,
                      const float* __restrict__ Wr,  const float* __restrict__ br,
                      const float* __restrict__ Wv,  const float* __restrict__ bv,
                      float* __restrict__ out, int G) {
    int g = blockIdx.x;
    int c = threadIdx.x;   // 64 threads
    __shared__ float hg[64], z1[64], z2[64];
    __shared__ float part[6];
    float cnt = fmaxf(g_cnt[g], 1.f);
    hg[c] = g_pool[g * 64 + c] / cnt;
    __syncthreads();
    float acc = bm1[c];
    #pragma unroll 8
    for (int k = 0; k < 64; k++) acc += hg[k] * Wm1[k * 64 + c];
    z1[c] = fmaxf(acc, 0.f);
    __syncthreads();
    acc = bm2[c];
    #pragma unroll 8
    for (int k = 0; k < 64; k++) acc += z1[k] * Wm2[k * 64 + c];
    z2[c] = fmaxf(acc, 0.f);
    __syncthreads();
    float vc = warp_sum(z2[c] * Wc[c]);
    float vr = warp_sum(z2[c] * Wr[c]);
    float vv = warp_sum(z2[c] * Wv[c]);
    if ((c & 31) == 0) {
        int w = c >> 5;
        part[w * 3 + 0] = vc; part[w * 3 + 1] = vr; part[w * 3 + 2] = vv;
    }
    __syncthreads();
    if (c == 0) {
        float cl = part[0] + part[3] + bc[0];
        float rt = part[1] + part[4] + br[0];
        float vo = part[2] + part[5] + bv[0];
        out[g]         = cl;
        out[G + g]     = rt;
        out[2 * G + g] = fmaxf(vo, 0.f) + log1pf(expf(-fabsf(vo)));  // softplus
    }
}

// ---------------- launch ----------------
extern "C" void kernel_launch(void* const* d_in, const int* in_sizes, int n_in,
                              void* d_out, int out_size) {
    const float* x    = (const float*)d_in[0];
    const void*  ei   = d_in[1];
    const void*  batch= d_in[2];
    const float* Wp   = (const float*)d_in[3];
    const float* bp   = (const float*)d_in[4];
    const float* W1   = (const float*)d_in[5];
    const float* as1  = (const float*)d_in[6];
    const float* ad1  = (const float*)d_in[7];
    const float* b1   = (const float*)d_in[8];
    const float* W2   = (const float*)d_in[9];
    const float* as2  = (const float*)d_in[10];
    const float* ad2  = (const float*)d_in[11];
    const float* b2   = (const float*)d_in[12];
    const float* Wm1  = (const float*)d_in[13];
    const float* bm1  = (const float*)d_in[14];
    const float* Wm2  = (const float*)d_in[15];
    const float* bm2  = (const float*)d_in[16];
    const float* Wc   = (const float*)d_in[17];
    const float* bc   = (const float*)d_in[18];
    const float* Wr   = (const float*)d_in[19];
    const float* br   = (const float*)d_in[20];
    const float* Wv   = (const float*)d_in[21];
    const float* bv   = (const float*)d_in[22];
    float* out = (float*)d_out;

    int n  = in_sizes[0] / 128;
    int e  = in_sizes[1] / 2;
    int G  = out_size / 3;
    int et = e + n;

    // real device addresses of __device__ globals
    void *p_offs, *p_pool, *p_cnt, *p_h0, *p_xh1, *p_out1, *p_xh2;
    cudaGetSymbolAddress(&p_offs, g_offs);
    cudaGetSymbolAddress(&p_pool, g_pool);
    cudaGetSymbolAddress(&p_cnt,  g_cnt);
    cudaGetSymbolAddress(&p_h0,   g_h0);
    cudaGetSymbolAddress(&p_xh1,  g_xh1);
    cudaGetSymbolAddress(&p_out1, g_out1);
    cudaGetSymbolAddress(&p_xh2,  g_xh2);
    float* d_h0   = (float*)p_h0;
    float* d_xh1  = (float*)p_xh1;
    float* d_out1 = (float*)p_out1;
    float* d_xh2  = (float*)p_xh2;

    const int GEMM128_SMEM = (128 * 64 + 128 * 36) * (int)sizeof(float);  // 51200 B
    cudaFuncSetAttribute(k_gemm_k128_m64, cudaFuncAttributeMaxDynamicSharedMemorySize, GEMM128_SMEM);

    cudaMemsetAsync(p_offs, 0, (size_t)(n + 1) * sizeof(int));
    cudaMemsetAsync(p_pool, 0, (size_t)G * 64 * sizeof(float));
    cudaMemsetAsync(p_cnt,  0, (size_t)G * sizeof(float));

    k_detect<<<1, 32>>>(ei);

    // CSR build
    k_hist <<<(et + 1023) / 1024, 256>>>(ei, e, et);
    k_scan <<<1, 1024>>>(n + 1);
    k_place<<<(et + 1023) / 1024, 256>>>(ei, e, et);

    // node projection: h0 = relu(x @ Wp + bp)
    k_gemm_k128_m64<<<(n + 31) / 32, 128, GEMM128_SMEM>>>(x, Wp, bp, nullptr, nullptr, d_h0, n, 0);
    // xh1 = h0 @ W1, fused att1 coefficients
    k_gemm_k64_m128<<<(n + 31) / 32, 128>>>(d_h0, W1, as1, ad1, d_xh1, n);
    // layer-1 aggregation -> h1 (elu fused)
    k_agg1<<<(n + 7) / 8, 256>>>(b1, n);
    // xh2 = h1 @ W2, fused att2 coefficients
    k_gemm_k128_m64<<<(n + 31) / 32, 128, GEMM128_SMEM>>>(d_out1, W2, nullptr, as2, ad2, d_xh2, n, 1);
    // layer-2 aggregation + elu + mean-pool
    k_agg2<<<(n + 7) / 8, 256>>>(b2, batch, n);

    k_mlp<<<G, 64>>>(Wm1, bm1, Wm2, bm2, Wc, bc, Wr, br, Wv, bv, out, G);
}

// round 5
// speedup vs baseline: 2.7615x; 1.1020x over previous
#include <cuda_runtime.h>
#include <math.h>

#define NMAX   50000
#define EMAX   800000
#define ETMAX  (EMAX + NMAX)
#define GMAX   1024

// ---------------- scratch ----------------
__device__ __align__(16) float g_h0 [NMAX * 64];     // relu(x@Wp+bp)
__device__ __align__(16) float g_xh1[NMAX * 128];    // h0@W1
__device__ __align__(16) float g_out1[NMAX * 128];   // h1 = elu(gat1)
__device__ __align__(16) float g_xh2[NMAX * 64];     // h1@W2
__device__ float g_as1[NMAX * 4];
__device__ float g_ad1[NMAX * 4];
__device__ float g_as2[NMAX];
__device__ float g_ad2[NMAX];
__device__ int   g_offs[NMAX + 1];
__device__ int   g_cursor[NMAX + 1];
__device__ int   g_csrc[ETMAX];
__device__ float g_pool[GMAX * 64];
__device__ float g_cnt [GMAX];
__device__ int   g_is64;

// ---------------- helpers ----------------
__device__ __forceinline__ int ld_idx(const void* p, long long i, int is64) {
    if (is64) return (int)((const long long*)p)[i];
    return ((const int*)p)[i];
}
__device__ __forceinline__ float eluf(float v) { return v > 0.f ? v : expm1f(v); }
__device__ __forceinline__ float warp_sum(float v) {
    #pragma unroll
    for (int o = 16; o > 0; o >>= 1) v += __shfl_down_sync(0xffffffffu, v, o);
    return v;
}

// ---------------- init: zero scratch + dtype detect (1 kernel) ----------------
__global__ void k_init(const void* ei, int n, int G) {
    if (blockIdx.x == 0 && threadIdx.x < 32) {
        const int* p = (const int*)ei;
        bool all0 = true;
        for (int i = threadIdx.x; i < 128; i += 32)
            if (p[2 * i + 1] != 0) all0 = false;
        all0 = __all_sync(0xffffffffu, all0);
        if (threadIdx.x == 0) g_is64 = all0 ? 1 : 0;
    }
    int total = (n + 1) + G * 64 + G;
    for (int i = blockIdx.x * blockDim.x + threadIdx.x; i < total; i += gridDim.x * blockDim.x) {
        if (i <= n)                 g_offs[i] = 0;
        else if (i <= n + G * 64)   g_pool[i - n - 1] = 0.f;
        else                        g_cnt [i - n - 1 - G * 64] = 0.f;
    }
}

// ---------------- CSR build ----------------
__global__ void k_hist(const void* __restrict__ ei, int e, int et) {
    int base = (blockIdx.x * blockDim.x + threadIdx.x) * 4;
    if (base >= et) return;
    int is64 = g_is64;
    #pragma unroll
    for (int u = 0; u < 4; u++) {
        int idx = base + u;
        if (idx >= et) break;
        int d = (idx < e) ? ld_idx(ei, (long long)e + idx, is64) : (idx - e);
        atomicAdd(&g_offs[d + 1], 1);
    }
}

__global__ void k_scan(int n1) {   // inclusive scan of g_offs[0..n1); also fills cursor
    __shared__ int part[1024];
    int t = threadIdx.x;
    int chunk = (n1 + 1023) >> 10;
    int beg = t * chunk;
    int end = beg + chunk; if (end > n1) end = n1;
    int s = 0;
    for (int i = beg; i < end; i++) s += g_offs[i];
    part[t] = s;
    __syncthreads();
    for (int off = 1; off < 1024; off <<= 1) {
        int v = (t >= off) ? part[t - off] : 0;
        __syncthreads();
        part[t] += v;
        __syncthreads();
    }
    int run = (t == 0) ? 0 : part[t - 1];
    for (int i = beg; i < end; i++) {
        run += g_offs[i];
        g_offs[i] = run;
        g_cursor[i] = run;
    }
}

__global__ void k_place(const void* __restrict__ ei, int e, int et) {
    int base = (blockIdx.x * blockDim.x + threadIdx.x) * 8;
    if (base >= et) return;
    int is64 = g_is64;
    int sv[8], dv[8];
    int m = et - base; if (m > 8) m = 8;
    #pragma unroll
    for (int u = 0; u < 8; u++) {
        if (u >= m) break;
        int idx = base + u;
        if (idx < e) { sv[u] = ld_idx(ei, idx, is64); dv[u] = ld_idx(ei, (long long)e + idx, is64); }
        else         { sv[u] = dv[u] = idx - e; }
    }
    int pos[8];
    #pragma unroll
    for (int u = 0; u < 8; u++) {
        if (u >= m) break;
        pos[u] = atomicAdd(&g_cursor[dv[u]], 1);
    }
    #pragma unroll
    for (int u = 0; u < 8; u++) {
        if (u >= m) break;
        g_csrc[pos[u]] = sv[u];
    }
}

// ============ GEMM A[n,128] @ W[128,64] -> out[n,64], 64 rows/block ============
// mode 0: += bias, relu (node projection)
// mode 1: no bias, write g_as2/g_ad2 = out @ as2 / out @ ad2 (xh2 + att2)
// dyn smem: sW[128*64] + sAt[128*68]
__global__ void __launch_bounds__(256) k_gemm_k128_m64(
        const float* __restrict__ A, const float* __restrict__ W,
        const float* __restrict__ bias,
        const float* __restrict__ av_s, const float* __restrict__ av_d,
        float* __restrict__ out, int n, int mode) {
    extern __shared__ float sm[];
    float* sW  = sm;              // [128][64]
    float* sAt = sm + 128 * 64;   // [k][r] stride 68
    int t = threadIdx.x;          // 256
    for (int i = t; i < 128 * 64; i += 256) sW[i] = W[i];
    int row0 = blockIdx.x * 64;
    for (int i = t; i < 64 * 128; i += 256) {
        int r = i >> 7, k = i & 127;
        float v = (row0 + r < n) ? A[(size_t)(row0 + r) * 128 + k] : 0.f;
        sAt[k * 68 + r] = v;
    }
    __syncthreads();
    int cg = t & 15, rg = t >> 4;      // 16 col-groups x 16 row-groups
    int c0 = cg * 4, r0 = rg * 4;
    float4 acc0 = make_float4(0.f,0.f,0.f,0.f), acc1 = acc0, acc2 = acc0, acc3 = acc0;
    #pragma unroll 4
    for (int k = 0; k < 128; k++) {
        float4 a4 = *(const float4*)&sAt[k * 68 + r0];
        float4 w4 = *(const float4*)&sW [k * 64 + c0];
        acc0.x += a4.x*w4.x; acc0.y += a4.x*w4.y; acc0.z += a4.x*w4.z; acc0.w += a4.x*w4.w;
        acc1.x += a4.y*w4.x; acc1.y += a4.y*w4.y; acc1.z += a4.y*w4.z; acc1.w += a4.y*w4.w;
        acc2.x += a4.z*w4.x; acc2.y += a4.z*w4.y; acc2.z += a4.z*w4.z; acc2.w += a4.z*w4.w;
        acc3.x += a4.w*w4.x; acc3.y += a4.w*w4.y; acc3.z += a4.w*w4.z; acc3.w += a4.w*w4.w;
    }
    float4 accs[4] = {acc0, acc1, acc2, acc3};
    if (mode == 0) {
        float4 bb;
        bb.x = bias[c0]; bb.y = bias[c0+1]; bb.z = bias[c0+2]; bb.w = bias[c0+3];
        #pragma unroll
        for (int j = 0; j < 4; j++) {
            int row = row0 + r0 + j;
            if (row < n) {
                float4 o = accs[j];
                o.x = fmaxf(o.x + bb.x, 0.f); o.y = fmaxf(o.y + bb.y, 0.f);
                o.z = fmaxf(o.z + bb.z, 0.f); o.w = fmaxf(o.w + bb.w, 0.f);
                *(float4*)&out[(size_t)row * 64 + c0] = o;
            }
        }
    } else {
        float4 sv, dv;
        sv.x = av_s[c0]; sv.y = av_s[c0+1]; sv.z = av_s[c0+2]; sv.w = av_s[c0+3];
        dv.x = av_d[c0]; dv.y = av_d[c0+1]; dv.z = av_d[c0+2]; dv.w = av_d[c0+3];
        #pragma unroll
        for (int j = 0; j < 4; j++) {
            int row = row0 + r0 + j;
            float4 o = accs[j];
            float ps = o.x*sv.x + o.y*sv.y + o.z*sv.z + o.w*sv.w;
            float pd = o.x*dv.x + o.y*dv.y + o.z*dv.z + o.w*dv.w;
            #pragma unroll
            for (int off = 1; off < 16; off <<= 1) {
                ps += __shfl_xor_sync(0xffffffffu, ps, off);
                pd += __shfl_xor_sync(0xffffffffu, pd, off);
            }
            if (row < n) {
                *(float4*)&out[(size_t)row * 64 + c0] = o;
                if (cg == 0) { g_as2[row] = ps; g_ad2[row] = pd; }
            }
        }
    }
}

// ============ GEMM A[n,64] @ W1[64,128] -> g_xh1[n,128] + att1, 64 rows/block ============
// dyn smem: sW[64*128] + sAt[64*68]
__global__ void __launch_bounds__(256) k_gemm_k64_m128(
        const float* __restrict__ A, const float* __restrict__ W,
        const float* __restrict__ av_s, const float* __restrict__ av_d,
        float* __restrict__ out, int n) {
    extern __shared__ float sm[];
    float* sW  = sm;              // [64][128]
    float* sAt = sm + 64 * 128;   // [k][r] stride 68
    int t = threadIdx.x;          // 256
    for (int i = t; i < 64 * 128; i += 256) sW[i] = W[i];
    int row0 = blockIdx.x * 64;
    for (int i = t; i < 64 * 64; i += 256) {
        int r = i >> 6, k = i & 63;
        float v = (row0 + r < n) ? A[(size_t)(row0 + r) * 64 + k] : 0.f;
        sAt[k * 68 + r] = v;
    }
    __syncthreads();
    int cg = t & 15, rg = t >> 4;
    int c0 = cg * 8, r0 = rg * 4;
    float4 aA0 = make_float4(0.f,0.f,0.f,0.f), aA1 = aA0, aA2 = aA0, aA3 = aA0;
    float4 aB0 = aA0, aB1 = aA0, aB2 = aA0, aB3 = aA0;
    #pragma unroll 4
    for (int k = 0; k < 64; k++) {
        float4 a4 = *(const float4*)&sAt[k * 68 + r0];
        float4 wa = *(const float4*)&sW [k * 128 + c0];
        float4 wb = *(const float4*)&sW [k * 128 + c0 + 4];
        aA0.x += a4.x*wa.x; aA0.y += a4.x*wa.y; aA0.z += a4.x*wa.z; aA0.w += a4.x*wa.w;
        aA1.x += a4.y*wa.x; aA1.y += a4.y*wa.y; aA1.z += a4.y*wa.z; aA1.w += a4.y*wa.w;
        aA2.x += a4.z*wa.x; aA2.y += a4.z*wa.y; aA2.z += a4.z*wa.z; aA2.w += a4.z*wa.w;
        aA3.x += a4.w*wa.x; aA3.y += a4.w*wa.y; aA3.z += a4.w*wa.z; aA3.w += a4.w*wa.w;
        aB0.x += a4.x*wb.x; aB0.y += a4.x*wb.y; aB0.z += a4.x*wb.z; aB0.w += a4.x*wb.w;
        aB1.x += a4.y*wb.x; aB1.y += a4.y*wb.y; aB1.z += a4.y*wb.z; aB1.w += a4.y*wb.w;
        aB2.x += a4.z*wb.x; aB2.y += a4.z*wb.y; aB2.z += a4.z*wb.z; aB2.w += a4.z*wb.w;
        aB3.x += a4.w*wb.x; aB3.y += a4.w*wb.y; aB3.z += a4.w*wb.z; aB3.w += a4.w*wb.w;
    }
    float4 A_[4] = {aA0, aA1, aA2, aA3};
    float4 B_[4] = {aB0, aB1, aB2, aB3};
    int head = cg >> 2;
    float4 s0, s1, d0, d1;
    s0.x=av_s[c0];   s0.y=av_s[c0+1]; s0.z=av_s[c0+2]; s0.w=av_s[c0+3];
    s1.x=av_s[c0+4]; s1.y=av_s[c0+5]; s1.z=av_s[c0+6]; s1.w=av_s[c0+7];
    d0.x=av_d[c0];   d0.y=av_d[c0+1]; d0.z=av_d[c0+2]; d0.w=av_d[c0+3];
    d1.x=av_d[c0+4]; d1.y=av_d[c0+5]; d1.z=av_d[c0+6]; d1.w=av_d[c0+7];
    #pragma unroll
    for (int j = 0; j < 4; j++) {
        int row = row0 + r0 + j;
        float4 oa = A_[j], ob = B_[j];
        float ps = oa.x*s0.x + oa.y*s0.y + oa.z*s0.z + oa.w*s0.w
                 + ob.x*s1.x + ob.y*s1.y + ob.z*s1.z + ob.w*s1.w;
        float pd = oa.x*d0.x + oa.y*d0.y + oa.z*d0.z + oa.w*d0.w
                 + ob.x*d1.x + ob.y*d1.y + ob.z*d1.z + ob.w*d1.w;
        ps += __shfl_xor_sync(0xffffffffu, ps, 1);
        ps += __shfl_xor_sync(0xffffffffu, ps, 2);
        pd += __shfl_xor_sync(0xffffffffu, pd, 1);
        pd += __shfl_xor_sync(0xffffffffu, pd, 2);
        if (row < n) {
            *(float4*)&out[(size_t)row * 128 + c0]     = oa;
            *(float4*)&out[(size_t)row * 128 + c0 + 4] = ob;
            if ((cg & 3) == 0) {
                g_as1[row * 4 + head] = ps;
                g_ad1[row * 4 + head] = pd;
            }
        }
    }
}

// ---------------- GAT1 aggregation: warp per dst node, 4-way unroll ----------------
__global__ void k_agg1(const float* __restrict__ b1, int n) {
    int node = blockIdx.x * 8 + (threadIdx.x >> 5);
    if (node >= n) return;
    int lane = threadIdx.x & 31;
    int h = lane >> 3;
    float ad = g_ad1[node * 4 + h];
    int beg = g_offs[node], end = g_offs[node + 1];
    const float4* xh4 = (const float4*)g_xh1;
    float4 acc[4];
    acc[0] = make_float4(0.f,0.f,0.f,0.f); acc[1] = acc[0]; acc[2] = acc[0]; acc[3] = acc[0];
    float ws[4] = {0.f, 0.f, 0.f, 0.f};
    int j = beg;
    for (; j + 3 < end; j += 4) {
        int s[4];
        s[0] = g_csrc[j]; s[1] = g_csrc[j+1]; s[2] = g_csrc[j+2]; s[3] = g_csrc[j+3];
        #pragma unroll
        for (int u = 0; u < 4; u++) {
            float e = g_as1[s[u] * 4 + h] + ad;
            e = e > 0.f ? e : 0.2f * e;
            float w = __expf(e);
            float4 v = xh4[(size_t)s[u] * 32 + lane];
            acc[u].x += w*v.x; acc[u].y += w*v.y; acc[u].z += w*v.z; acc[u].w += w*v.w;
            ws[u] += w;
        }
    }
    for (; j < end; j++) {
        int s0 = g_csrc[j];
        float e = g_as1[s0 * 4 + h] + ad;
        e = e > 0.f ? e : 0.2f * e;
        float w = __expf(e);
        float4 v = xh4[(size_t)s0 * 32 + lane];
        acc[0].x += w*v.x; acc[0].y += w*v.y; acc[0].z += w*v.z; acc[0].w += w*v.w;
        ws[0] += w;
    }
    float inv = 1.f / (ws[0] + ws[1] + ws[2] + ws[3] + 1e-16f);
    float4 bb = ((const float4*)b1)[lane];
    float4 o;
    o.x = eluf((acc[0].x + acc[1].x + acc[2].x + acc[3].x) * inv + bb.x);
    o.y = eluf((acc[0].y + acc[1].y + acc[2].y + acc[3].y) * inv + bb.y);
    o.z = eluf((acc[0].z + acc[1].z + acc[2].z + acc[3].z) * inv + bb.z);
    o.w = eluf((acc[0].w + acc[1].w + acc[2].w + acc[3].w) * inv + bb.w);
    ((float4*)g_out1)[(size_t)node * 32 + lane] = o;
}

// ---------------- GAT2 aggregation + elu + mean-pool scatter ----------------
__global__ void k_agg2(const float* __restrict__ b2, const void* __restrict__ batch, int n) {
    int node = blockIdx.x * 8 + (threadIdx.x >> 5);
    if (node >= n) return;
    int lane = threadIdx.x & 31;
    float ad = g_ad2[node];
    int beg = g_offs[node], end = g_offs[node + 1];
    const float2* xh2 = (const float2*)g_xh2;
    float2 acc[4];
    acc[0] = make_float2(0.f,0.f); acc[1] = acc[0]; acc[2] = acc[0]; acc[3] = acc[0];
    float ws[4] = {0.f, 0.f, 0.f, 0.f};
    int j = beg;
    for (; j + 3 < end; j += 4) {
        int s[4];
        s[0] = g_csrc[j]; s[1] = g_csrc[j+1]; s[2] = g_csrc[j+2]; s[3] = g_csrc[j+3];
        #pragma unroll
        for (int u = 0; u < 4; u++) {
            float e = g_as2[s[u]] + ad;
            e = e > 0.f ? e : 0.2f * e;
            float w = __expf(e);
            float2 v = xh2[(size_t)s[u] * 32 + lane];
            acc[u].x += w*v.x; acc[u].y += w*v.y;
            ws[u] += w;
        }
    }
    for (; j < end; j++) {
        int s0 = g_csrc[j];
        float e = g_as2[s0] + ad;
        e = e > 0.f ? e : 0.2f * e;
        float w = __expf(e);
        float2 v = xh2[(size_t)s0 * 32 + lane];
        acc[0].x += w*v.x; acc[0].y += w*v.y;
        ws[0] += w;
    }
    float inv = 1.f / (ws[0] + ws[1] + ws[2] + ws[3] + 1e-16f);
    float2 bb = ((const float2*)b2)[lane];
    float ox = eluf((acc[0].x + acc[1].x + acc[2].x + acc[3].x) * inv + bb.x);
    float oy = eluf((acc[0].y + acc[1].y + acc[2].y + acc[3].y) * inv + bb.y);
    int b = ld_idx(batch, node, g_is64);
    atomicAdd(&g_pool[b * 64 + lane * 2], ox);
    atomicAdd(&g_pool[b * 64 + lane * 2 + 1], oy);
    if (lane == 0) atomicAdd(&g_cnt[b], 1.0f);
}

// ---------------- graph-level MLP + heads ----------------
__global__ void k_mlp(const float* __restrict__ Wm1, const float* __restrict__ bm1,
                      const float* __restrict__ Wm2, const float* __restrict__ bm2,
                      const float* __restrict__ Wc,  const float* __restrict__ bc,
                      const float* __restrict__ Wr,  const float* __restrict__ br,
                      const float* __restrict__ Wv,  const float* __restrict__ bv,
                      float* __restrict__ out, int G) {
    int g = blockIdx.x;
    int c = threadIdx.x;   // 64 threads
    __shared__ float hg[64], z1[64], z2[64];
    __shared__ float part[6];
    float cnt = fmaxf(g_cnt[g], 1.f);
    hg[c] = g_pool[g * 64 + c] / cnt;
    __syncthreads();
    float acc = bm1[c];
    #pragma unroll 8
    for (int k = 0; k < 64; k++) acc += hg[k] * Wm1[k * 64 + c];
    z1[c] = fmaxf(acc, 0.f);
    __syncthreads();
    acc = bm2[c];
    #pragma unroll 8
    for (int k = 0; k < 64; k++) acc += z1[k] * Wm2[k * 64 + c];
    z2[c] = fmaxf(acc, 0.f);
    __syncthreads();
    float vc = warp_sum(z2[c] * Wc[c]);
    float vr = warp_sum(z2[c] * Wr[c]);
    float vv = warp_sum(z2[c] * Wv[c]);
    if ((c & 31) == 0) {
        int w = c >> 5;
        part[w * 3 + 0] = vc; part[w * 3 + 1] = vr; part[w * 3 + 2] = vv;
    }
    __syncthreads();
    if (c == 0) {
        float cl = part[0] + part[3] + bc[0];
        float rt = part[1] + part[4] + br[0];
        float vo = part[2] + part[5] + bv[0];
        out[g]         = cl;
        out[G + g]     = rt;
        out[2 * G + g] = fmaxf(vo, 0.f) + log1pf(expf(-fabsf(vo)));  // softplus
    }
}

// ---------------- launch ----------------
extern "C" void kernel_launch(void* const* d_in, const int* in_sizes, int n_in,
                              void* d_out, int out_size) {
    const float* x    = (const float*)d_in[0];
    const void*  ei   = d_in[1];
    const void*  batch= d_in[2];
    const float* Wp   = (const float*)d_in[3];
    const float* bp   = (const float*)d_in[4];
    const float* W1   = (const float*)d_in[5];
    const float* as1  = (const float*)d_in[6];
    const float* ad1  = (const float*)d_in[7];
    const float* b1   = (const float*)d_in[8];
    const float* W2   = (const float*)d_in[9];
    const float* as2  = (const float*)d_in[10];
    const float* ad2  = (const float*)d_in[11];
    const float* b2   = (const float*)d_in[12];
    const float* Wm1  = (const float*)d_in[13];
    const float* bm1  = (const float*)d_in[14];
    const float* Wm2  = (const float*)d_in[15];
    const float* bm2  = (const float*)d_in[16];
    const float* Wc   = (const float*)d_in[17];
    const float* bc   = (const float*)d_in[18];
    const float* Wr   = (const float*)d_in[19];
    const float* br   = (const float*)d_in[20];
    const float* Wv   = (const float*)d_in[21];
    const float* bv   = (const float*)d_in[22];
    float* out = (float*)d_out;

    int n  = in_sizes[0] / 128;
    int e  = in_sizes[1] / 2;
    int G  = out_size / 3;
    int et = e + n;

    // real device addresses of __device__ globals
    void *p_h0, *p_xh1, *p_out1, *p_xh2;
    cudaGetSymbolAddress(&p_h0,   g_h0);
    cudaGetSymbolAddress(&p_xh1,  g_xh1);
    cudaGetSymbolAddress(&p_out1, g_out1);
    cudaGetSymbolAddress(&p_xh2,  g_xh2);
    float* d_h0   = (float*)p_h0;
    float* d_xh1  = (float*)p_xh1;
    float* d_out1 = (float*)p_out1;
    float* d_xh2  = (float*)p_xh2;

    const int G128_SMEM = (128 * 64 + 128 * 68) * (int)sizeof(float);  // 67584 B
    const int G64_SMEM  = (64 * 128 + 64 * 68)  * (int)sizeof(float);  // 50176 B
    cudaFuncSetAttribute(k_gemm_k128_m64, cudaFuncAttributeMaxDynamicSharedMemorySize, G128_SMEM);
    cudaFuncSetAttribute(k_gemm_k64_m128, cudaFuncAttributeMaxDynamicSharedMemorySize, G64_SMEM);

    // init (zero offs/pool/cnt + dtype detect)
    k_init<<<160, 256>>>(ei, n, G);

    // CSR build
    k_hist <<<(et + 1023) / 1024, 256>>>(ei, e, et);
    k_scan <<<1, 1024>>>(n + 1);
    k_place<<<(et + 2047) / 2048, 256>>>(ei, e, et);

    // node projection: h0 = relu(x @ Wp + bp)
    k_gemm_k128_m64<<<(n + 63) / 64, 256, G128_SMEM>>>(x, Wp, bp, nullptr, nullptr, d_h0, n, 0);
    // xh1 = h0 @ W1 + fused att1
    k_gemm_k64_m128<<<(n + 63) / 64, 256, G64_SMEM>>>(d_h0, W1, as1, ad1, d_xh1, n);
    // layer-1 aggregation -> h1 (elu fused)
    k_agg1<<<(n + 7) / 8, 256>>>(b1, n);
    // xh2 = h1 @ W2 + fused att2
    k_gemm_k128_m64<<<(n + 63) / 64, 256, G128_SMEM>>>(d_out1, W2, nullptr, as2, ad2, d_xh2, n, 1);
    // layer-2 aggregation + elu + mean-pool
    k_agg2<<<(n + 7) / 8, 256>>>(b2, batch, n);

    k_mlp<<<G, 64>>>(Wm1, bm1, Wm2, bm2, Wc, bc, Wr, br, Wv, bv, out, G);
}

// round 6
// speedup vs baseline: 3.4355x; 1.2441x over previous
#include <cuda_runtime.h>
#include <cuda_bf16.h>
#include <math.h>

#define NMAX   50000
#define EMAX   800000
#define ETMAX  (EMAX + NMAX)
#define GMAX   1024

// ---------------- scratch ----------------
__device__ __align__(16) float         g_h0 [NMAX * 64];   // relu(x@Wp+bp), fp32
__device__ __align__(16) __nv_bfloat16 g_xh1[NMAX * 128];  // h0@W1 (bf16 payload)
__device__ __align__(16) float         g_out1[NMAX * 128]; // h1 = elu(gat1), fp32
__device__ __align__(16) __nv_bfloat16 g_xh2[NMAX * 64];   // h1@W2 (bf16 payload)
__device__ float g_as1[NMAX * 4];
__device__ float g_ad1[NMAX * 4];
__device__ float g_as2[NMAX];
__device__ float g_ad2[NMAX];
__device__ int   g_offs[NMAX + 1];
__device__ int   g_cursor[NMAX + 1];
__device__ int   g_csrc[ETMAX];
__device__ float g_pool[GMAX * 64];
__device__ float g_cnt [GMAX];
__device__ int   g_is64;

// ---------------- helpers ----------------
__device__ __forceinline__ int ld_idx(const void* p, long long i, int is64) {
    if (is64) return (int)((const long long*)p)[i];
    return ((const int*)p)[i];
}
__device__ __forceinline__ float eluf(float v) { return v > 0.f ? v : expm1f(v); }
__device__ __forceinline__ float warp_sum(float v) {
    #pragma unroll
    for (int o = 16; o > 0; o >>= 1) v += __shfl_down_sync(0xffffffffu, v, o);
    return v;
}
__device__ __forceinline__ unsigned pack_bf16x2(float a, float b) {
    __nv_bfloat162 p = __float22bfloat162_rn(make_float2(a, b));
    return *reinterpret_cast<unsigned*>(&p);
}
__device__ __forceinline__ float2 unpack_bf16x2(unsigned u) {
    __nv_bfloat162 p = *reinterpret_cast<__nv_bfloat162*>(&u);
    return __bfloat1622float2(p);
}

// ---------------- init: zero scratch + dtype detect (1 kernel) ----------------
__global__ void k_init(const void* ei, int n, int G) {
    if (blockIdx.x == 0 && threadIdx.x < 32) {
        const int* p = (const int*)ei;
        bool all0 = true;
        for (int i = threadIdx.x; i < 128; i += 32)
            if (p[2 * i + 1] != 0) all0 = false;
        all0 = __all_sync(0xffffffffu, all0);
        if (threadIdx.x == 0) g_is64 = all0 ? 1 : 0;
    }
    int total = (n + 1) + G * 64 + G;
    for (int i = blockIdx.x * blockDim.x + threadIdx.x; i < total; i += gridDim.x * blockDim.x) {
        if (i <= n)                 g_offs[i] = 0;
        else if (i <= n + G * 64)   g_pool[i - n - 1] = 0.f;
        else                        g_cnt [i - n - 1 - G * 64] = 0.f;
    }
}

// ---------------- CSR build ----------------
__global__ void k_hist(const void* __restrict__ ei, int e, int et) {
    int base = (blockIdx.x * blockDim.x + threadIdx.x) * 4;
    if (base >= et) return;
    int is64 = g_is64;
    #pragma unroll
    for (int u = 0; u < 4; u++) {
        int idx = base + u;
        if (idx >= et) break;
        int d = (idx < e) ? ld_idx(ei, (long long)e + idx, is64) : (idx - e);
        atomicAdd(&g_offs[d + 1], 1);
    }
}

__global__ void k_scan(int n1) {   // inclusive scan of g_offs[0..n1); also fills cursor
    __shared__ int part[1024];
    int t = threadIdx.x;
    int chunk = (n1 + 1023) >> 10;
    int beg = t * chunk;
    int end = beg + chunk; if (end > n1) end = n1;
    int s = 0;
    for (int i = beg; i < end; i++) s += g_offs[i];
    part[t] = s;
    __syncthreads();
    for (int off = 1; off < 1024; off <<= 1) {
        int v = (t >= off) ? part[t - off] : 0;
        __syncthreads();
        part[t] += v;
        __syncthreads();
    }
    int run = (t == 0) ? 0 : part[t - 1];
    for (int i = beg; i < end; i++) {
        run += g_offs[i];
        g_offs[i] = run;
        g_cursor[i] = run;
    }
}

__global__ void k_place(const void* __restrict__ ei, int e, int et) {
    int base = (blockIdx.x * blockDim.x + threadIdx.x) * 8;
    if (base >= et) return;
    int is64 = g_is64;
    int sv[8], dv[8];
    int m = et - base; if (m > 8) m = 8;
    #pragma unroll
    for (int u = 0; u < 8; u++) {
        if (u >= m) break;
        int idx = base + u;
        if (idx < e) { sv[u] = ld_idx(ei, idx, is64); dv[u] = ld_idx(ei, (long long)e + idx, is64); }
        else         { sv[u] = dv[u] = idx - e; }
    }
    int pos[8];
    #pragma unroll
    for (int u = 0; u < 8; u++) {
        if (u >= m) break;
        pos[u] = atomicAdd(&g_cursor[dv[u]], 1);
    }
    #pragma unroll
    for (int u = 0; u < 8; u++) {
        if (u >= m) break;
        g_csrc[pos[u]] = sv[u];
    }
}

// ============ GEMM A[n,128] @ W[128,64], 64 rows/block ============
// mode 0: out fp32 = relu(acc + bias)  (node projection)
// mode 1: out bf16 = acc; write g_as2/g_ad2 = acc@av_s / acc@av_d (xh2 + att2)
__global__ void __launch_bounds__(256) k_gemm_k128_m64(
        const float* __restrict__ A, const float* __restrict__ W,
        const float* __restrict__ bias,
        const float* __restrict__ av_s, const float* __restrict__ av_d,
        void* __restrict__ outp, int n, int mode) {
    extern __shared__ float sm[];
    float* sW  = sm;              // [128][64]
    float* sAt = sm + 128 * 64;   // [k][r] stride 68
    int t = threadIdx.x;          // 256
    for (int i = t; i < 128 * 64; i += 256) sW[i] = W[i];
    int row0 = blockIdx.x * 64;
    for (int i = t; i < 64 * 128; i += 256) {
        int r = i >> 7, k = i & 127;
        float v = (row0 + r < n) ? A[(size_t)(row0 + r) * 128 + k] : 0.f;
        sAt[k * 68 + r] = v;
    }
    __syncthreads();
    int cg = t & 15, rg = t >> 4;
    int c0 = cg * 4, r0 = rg * 4;
    float4 acc0 = make_float4(0.f,0.f,0.f,0.f), acc1 = acc0, acc2 = acc0, acc3 = acc0;
    #pragma unroll 4
    for (int k = 0; k < 128; k++) {
        float4 a4 = *(const float4*)&sAt[k * 68 + r0];
        float4 w4 = *(const float4*)&sW [k * 64 + c0];
        acc0.x += a4.x*w4.x; acc0.y += a4.x*w4.y; acc0.z += a4.x*w4.z; acc0.w += a4.x*w4.w;
        acc1.x += a4.y*w4.x; acc1.y += a4.y*w4.y; acc1.z += a4.y*w4.z; acc1.w += a4.y*w4.w;
        acc2.x += a4.z*w4.x; acc2.y += a4.z*w4.y; acc2.z += a4.z*w4.z; acc2.w += a4.z*w4.w;
        acc3.x += a4.w*w4.x; acc3.y += a4.w*w4.y; acc3.z += a4.w*w4.z; acc3.w += a4.w*w4.w;
    }
    float4 accs[4] = {acc0, acc1, acc2, acc3};
    if (mode == 0) {
        float* out = (float*)outp;
        float4 bb;
        bb.x = bias[c0]; bb.y = bias[c0+1]; bb.z = bias[c0+2]; bb.w = bias[c0+3];
        #pragma unroll
        for (int j = 0; j < 4; j++) {
            int row = row0 + r0 + j;
            if (row < n) {
                float4 o = accs[j];
                o.x = fmaxf(o.x + bb.x, 0.f); o.y = fmaxf(o.y + bb.y, 0.f);
                o.z = fmaxf(o.z + bb.z, 0.f); o.w = fmaxf(o.w + bb.w, 0.f);
                *(float4*)&out[(size_t)row * 64 + c0] = o;
            }
        }
    } else {
        __nv_bfloat16* out = (__nv_bfloat16*)outp;
        float4 sv, dv;
        sv.x = av_s[c0]; sv.y = av_s[c0+1]; sv.z = av_s[c0+2]; sv.w = av_s[c0+3];
        dv.x = av_d[c0]; dv.y = av_d[c0+1]; dv.z = av_d[c0+2]; dv.w = av_d[c0+3];
        #pragma unroll
        for (int j = 0; j < 4; j++) {
            int row = row0 + r0 + j;
            float4 o = accs[j];
            float ps = o.x*sv.x + o.y*sv.y + o.z*sv.z + o.w*sv.w;
            float pd = o.x*dv.x + o.y*dv.y + o.z*dv.z + o.w*dv.w;
            #pragma unroll
            for (int off = 1; off < 16; off <<= 1) {
                ps += __shfl_xor_sync(0xffffffffu, ps, off);
                pd += __shfl_xor_sync(0xffffffffu, pd, off);
            }
            if (row < n) {
                uint2 pk;
                pk.x = pack_bf16x2(o.x, o.y);
                pk.y = pack_bf16x2(o.z, o.w);
                *(uint2*)&out[(size_t)row * 64 + c0] = pk;
                if (cg == 0) { g_as2[row] = ps; g_ad2[row] = pd; }
            }
        }
    }
}

// ============ GEMM A[n,64] @ W1[64,128] -> g_xh1 bf16 + att1, 64 rows/block ============
__global__ void __launch_bounds__(256) k_gemm_k64_m128(
        const float* __restrict__ A, const float* __restrict__ W,
        const float* __restrict__ av_s, const float* __restrict__ av_d,
        __nv_bfloat16* __restrict__ out, int n) {
    extern __shared__ float sm[];
    float* sW  = sm;              // [64][128]
    float* sAt = sm + 64 * 128;   // [k][r] stride 68
    int t = threadIdx.x;          // 256
    for (int i = t; i < 64 * 128; i += 256) sW[i] = W[i];
    int row0 = blockIdx.x * 64;
    for (int i = t; i < 64 * 64; i += 256) {
        int r = i >> 6, k = i & 63;
        float v = (row0 + r < n) ? A[(size_t)(row0 + r) * 64 + k] : 0.f;
        sAt[k * 68 + r] = v;
    }
    __syncthreads();
    int cg = t & 15, rg = t >> 4;
    int c0 = cg * 8, r0 = rg * 4;
    float4 aA0 = make_float4(0.f,0.f,0.f,0.f), aA1 = aA0, aA2 = aA0, aA3 = aA0;
    float4 aB0 = aA0, aB1 = aA0, aB2 = aA0, aB3 = aA0;
    #pragma unroll 4
    for (int k = 0; k < 64; k++) {
        float4 a4 = *(const float4*)&sAt[k * 68 + r0];
        float4 wa = *(const float4*)&sW [k * 128 + c0];
        float4 wb = *(const float4*)&sW [k * 128 + c0 + 4];
        aA0.x += a4.x*wa.x; aA0.y += a4.x*wa.y; aA0.z += a4.x*wa.z; aA0.w += a4.x*wa.w;
        aA1.x += a4.y*wa.x; aA1.y += a4.y*wa.y; aA1.z += a4.y*wa.z; aA1.w += a4.y*wa.w;
        aA2.x += a4.z*wa.x; aA2.y += a4.z*wa.y; aA2.z += a4.z*wa.z; aA2.w += a4.z*wa.w;
        aA3.x += a4.w*wa.x; aA3.y += a4.w*wa.y; aA3.z += a4.w*wa.z; aA3.w += a4.w*wa.w;
        aB0.x += a4.x*wb.x; aB0.y += a4.x*wb.y; aB0.z += a4.x*wb.z; aB0.w += a4.x*wb.w;
        aB1.x += a4.y*wb.x; aB1.y += a4.y*wb.y; aB1.z += a4.y*wb.z; aB1.w += a4.y*wb.w;
        aB2.x += a4.z*wb.x; aB2.y += a4.z*wb.y; aB2.z += a4.z*wb.z; aB2.w += a4.z*wb.w;
        aB3.x += a4.w*wb.x; aB3.y += a4.w*wb.y; aB3.z += a4.w*wb.z; aB3.w += a4.w*wb.w;
    }
    float4 A_[4] = {aA0, aA1, aA2, aA3};
    float4 B_[4] = {aB0, aB1, aB2, aB3};
    int head = cg >> 2;
    float4 s0, s1, d0, d1;
    s0.x=av_s[c0];   s0.y=av_s[c0+1]; s0.z=av_s[c0+2]; s0.w=av_s[c0+3];
    s1.x=av_s[c0+4]; s1.y=av_s[c0+5]; s1.z=av_s[c0+6]; s1.w=av_s[c0+7];
    d0.x=av_d[c0];   d0.y=av_d[c0+1]; d0.z=av_d[c0+2]; d0.w=av_d[c0+3];
    d1.x=av_d[c0+4]; d1.y=av_d[c0+5]; d1.z=av_d[c0+6]; d1.w=av_d[c0+7];
    #pragma unroll
    for (int j = 0; j < 4; j++) {
        int row = row0 + r0 + j;
        float4 oa = A_[j], ob = B_[j];
        float ps = oa.x*s0.x + oa.y*s0.y + oa.z*s0.z + oa.w*s0.w
                 + ob.x*s1.x + ob.y*s1.y + ob.z*s1.z + ob.w*s1.w;
        float pd = oa.x*d0.x + oa.y*d0.y + oa.z*d0.z + oa.w*d0.w
                 + ob.x*d1.x + ob.y*d1.y + ob.z*d1.z + ob.w*d1.w;
        ps += __shfl_xor_sync(0xffffffffu, ps, 1);
        ps += __shfl_xor_sync(0xffffffffu, ps, 2);
        pd += __shfl_xor_sync(0xffffffffu, pd, 1);
        pd += __shfl_xor_sync(0xffffffffu, pd, 2);
        if (row < n) {
            uint4 pk;
            pk.x = pack_bf16x2(oa.x, oa.y);
            pk.y = pack_bf16x2(oa.z, oa.w);
            pk.z = pack_bf16x2(ob.x, ob.y);
            pk.w = pack_bf16x2(ob.z, ob.w);
            *(uint4*)&out[(size_t)row * 128 + c0] = pk;
            if ((cg & 3) == 0) {
                g_as1[row * 4 + head] = ps;
                g_ad1[row * 4 + head] = pd;
            }
        }
    }
}

// ---------------- GAT1 aggregation: warp per dst node (bf16 payload) ----------------
__global__ void k_agg1(const float* __restrict__ b1, int n) {
    int node = blockIdx.x * 8 + (threadIdx.x >> 5);
    if (node >= n) return;
    int lane = threadIdx.x & 31;
    int h = lane >> 3;            // lane handles 4 channels of head h
    float ad = g_ad1[node * 4 + h];
    int beg = g_offs[node], end = g_offs[node + 1];
    const uint2* xh = (const uint2*)g_xh1;   // 4 bf16 per lane per row
    float4 acc[4];
    acc[0] = make_float4(0.f,0.f,0.f,0.f); acc[1] = acc[0]; acc[2] = acc[0]; acc[3] = acc[0];
    float ws[4] = {0.f, 0.f, 0.f, 0.f};
    int j = beg;
    for (; j + 3 < end; j += 4) {
        int s[4];
        s[0] = g_csrc[j]; s[1] = g_csrc[j+1]; s[2] = g_csrc[j+2]; s[3] = g_csrc[j+3];
        #pragma unroll
        for (int u = 0; u < 4; u++) {
            float e = g_as1[s[u] * 4 + h] + ad;
            e = e > 0.f ? e : 0.2f * e;
            float w = __expf(e);
            uint2 pv = xh[(size_t)s[u] * 32 + lane];
            float2 v0 = unpack_bf16x2(pv.x);
            float2 v1 = unpack_bf16x2(pv.y);
            acc[u].x += w*v0.x; acc[u].y += w*v0.y; acc[u].z += w*v1.x; acc[u].w += w*v1.y;
            ws[u] += w;
        }
    }
    for (; j < end; j++) {
        int s0 = g_csrc[j];
        float e = g_as1[s0 * 4 + h] + ad;
        e = e > 0.f ? e : 0.2f * e;
        float w = __expf(e);
        uint2 pv = xh[(size_t)s0 * 32 + lane];
        float2 v0 = unpack_bf16x2(pv.x);
        float2 v1 = unpack_bf16x2(pv.y);
        acc[0].x += w*v0.x; acc[0].y += w*v0.y; acc[0].z += w*v1.x; acc[0].w += w*v1.y;
        ws[0] += w;
    }
    float inv = 1.f / (ws[0] + ws[1] + ws[2] + ws[3] + 1e-16f);
    float4 bb = ((const float4*)b1)[lane];
    float4 o;
    o.x = eluf((acc[0].x + acc[1].x + acc[2].x + acc[3].x) * inv + bb.x);
    o.y = eluf((acc[0].y + acc[1].y + acc[2].y + acc[3].y) * inv + bb.y);
    o.z = eluf((acc[0].z + acc[1].z + acc[2].z + acc[3].z) * inv + bb.z);
    o.w = eluf((acc[0].w + acc[1].w + acc[2].w + acc[3].w) * inv + bb.w);
    ((float4*)g_out1)[(size_t)node * 32 + lane] = o;
}

// ---------------- GAT2 aggregation + elu + mean-pool scatter (bf16 payload) ----------------
__global__ void k_agg2(const float* __restrict__ b2, const void* __restrict__ batch, int n) {
    int node = blockIdx.x * 8 + (threadIdx.x >> 5);
    if (node >= n) return;
    int lane = threadIdx.x & 31;
    float ad = g_ad2[node];
    int beg = g_offs[node], end = g_offs[node + 1];
    const unsigned* xh = (const unsigned*)g_xh2;   // 2 bf16 per lane per row
    float2 acc[4];
    acc[0] = make_float2(0.f,0.f); acc[1] = acc[0]; acc[2] = acc[0]; acc[3] = acc[0];
    float ws[4] = {0.f, 0.f, 0.f, 0.f};
    int j = beg;
    for (; j + 3 < end; j += 4) {
        int s[4];
        s[0] = g_csrc[j]; s[1] = g_csrc[j+1]; s[2] = g_csrc[j+2]; s[3] = g_csrc[j+3];
        #pragma unroll
        for (int u = 0; u < 4; u++) {
            float e = g_as2[s[u]] + ad;
            e = e > 0.f ? e : 0.2f * e;
            float w = __expf(e);
            float2 v = unpack_bf16x2(xh[(size_t)s[u] * 32 + lane]);
            acc[u].x += w*v.x; acc[u].y += w*v.y;
            ws[u] += w;
        }
    }
    for (; j < end; j++) {
        int s0 = g_csrc[j];
        float e = g_as2[s0] + ad;
        e = e > 0.f ? e : 0.2f * e;
        float w = __expf(e);
        float2 v = unpack_bf16x2(xh[(size_t)s0 * 32 + lane]);
        acc[0].x += w*v.x; acc[0].y += w*v.y;
        ws[0] += w;
    }
    float inv = 1.f / (ws[0] + ws[1] + ws[2] + ws[3] + 1e-16f);
    float2 bb = ((const float2*)b2)[lane];
    float ox = eluf((acc[0].x + acc[1].x + acc[2].x + acc[3].x) * inv + bb.x);
    float oy = eluf((acc[0].y + acc[1].y + acc[2].y + acc[3].y) * inv + bb.y);
    int b = ld_idx(batch, node, g_is64);
    atomicAdd(&g_pool[b * 64 + lane * 2], ox);
    atomicAdd(&g_pool[b * 64 + lane * 2 + 1], oy);
    if (lane == 0) atomicAdd(&g_cnt[b], 1.0f);
}

// ---------------- graph-level MLP + heads ----------------
__global__ void k_mlp(const float* __restrict__ Wm1, const float* __restrict__ bm1,
                      const float* __restrict__ Wm2, const float* __restrict__ bm2,
                      const float* __restrict__ Wc,  const float* __restrict__ bc,
                      const float* __restrict__ Wr,  const float* __restrict__ br,
                      const float* __restrict__ Wv,  const float* __restrict__ bv,
                      float* __restrict__ out, int G) {
    int g = blockIdx.x;
    int c = threadIdx.x;   // 64 threads
    __shared__ float hg[64], z1[64], z2[64];
    __shared__ float part[6];
    float cnt = fmaxf(g_cnt[g], 1.f);
    hg[c] = g_pool[g * 64 + c] / cnt;
    __syncthreads();
    float acc = bm1[c];
    #pragma unroll 8
    for (int k = 0; k < 64; k++) acc += hg[k] * Wm1[k * 64 + c];
    z1[c] = fmaxf(acc, 0.f);
    __syncthreads();
    acc = bm2[c];
    #pragma unroll 8
    for (int k = 0; k < 64; k++) acc += z1[k] * Wm2[k * 64 + c];
    z2[c] = fmaxf(acc, 0.f);
    __syncthreads();
    float vc = warp_sum(z2[c] * Wc[c]);
    float vr = warp_sum(z2[c] * Wr[c]);
    float vv = warp_sum(z2[c] * Wv[c]);
    if ((c & 31) == 0) {
        int w = c >> 5;
        part[w * 3 + 0] = vc; part[w * 3 + 1] = vr; part[w * 3 + 2] = vv;
    }
    __syncthreads();
    if (c == 0) {
        float cl = part[0] + part[3] + bc[0];
        float rt = part[1] + part[4] + br[0];
        float vo = part[2] + part[5] + bv[0];
        out[g]         = cl;
        out[G + g]     = rt;
        out[2 * G + g] = fmaxf(vo, 0.f) + log1pf(expf(-fabsf(vo)));  // softplus
    }
}

// ---------------- launch ----------------
extern "C" void kernel_launch(void* const* d_in, const int* in_sizes, int n_in,
                              void* d_out, int out_size) {
    const float* x    = (const float*)d_in[0];
    const void*  ei   = d_in[1];
    const void*  batch= d_in[2];
    const float* Wp   = (const float*)d_in[3];
    const float* bp   = (const float*)d_in[4];
    const float* W1   = (const float*)d_in[5];
    const float* as1  = (const float*)d_in[6];
    const float* ad1  = (const float*)d_in[7];
    const float* b1   = (const float*)d_in[8];
    const float* W2   = (const float*)d_in[9];
    const float* as2  = (const float*)d_in[10];
    const float* ad2  = (const float*)d_in[11];
    const float* b2   = (const float*)d_in[12];
    const float* Wm1  = (const float*)d_in[13];
    const float* bm1  = (const float*)d_in[14];
    const float* Wm2  = (const float*)d_in[15];
    const float* bm2  = (const float*)d_in[16];
    const float* Wc   = (const float*)d_in[17];
    const float* bc   = (const float*)d_in[18];
    const float* Wr   = (const float*)d_in[19];
    const float* br   = (const float*)d_in[20];
    const float* Wv   = (const float*)d_in[21];
    const float* bv   = (const float*)d_in[22];
    float* out = (float*)d_out;

    int n  = in_sizes[0] / 128;
    int e  = in_sizes[1] / 2;
    int G  = out_size / 3;
    int et = e + n;

    void *p_h0, *p_xh1, *p_out1, *p_xh2;
    cudaGetSymbolAddress(&p_h0,   g_h0);
    cudaGetSymbolAddress(&p_xh1,  g_xh1);
    cudaGetSymbolAddress(&p_out1, g_out1);
    cudaGetSymbolAddress(&p_xh2,  g_xh2);
    float*         d_h0   = (float*)p_h0;
    __nv_bfloat16* d_xh1  = (__nv_bfloat16*)p_xh1;
    float*         d_out1 = (float*)p_out1;
    __nv_bfloat16* d_xh2  = (__nv_bfloat16*)p_xh2;

    const int G128_SMEM = (128 * 64 + 128 * 68) * (int)sizeof(float);
    const int G64_SMEM  = (64 * 128 + 64 * 68)  * (int)sizeof(float);
    cudaFuncSetAttribute(k_gemm_k128_m64, cudaFuncAttributeMaxDynamicSharedMemorySize, G128_SMEM);
    cudaFuncSetAttribute(k_gemm_k64_m128, cudaFuncAttributeMaxDynamicSharedMemorySize, G64_SMEM);

    // fork stream: CSR chain (default) || GEMM chain (s2)
    cudaStream_t s2;
    cudaStreamCreateWithFlags(&s2, cudaStreamNonBlocking);
    cudaEvent_t evFork, evJoin;
    cudaEventCreateWithFlags(&evFork, cudaEventDisableTiming);
    cudaEventCreateWithFlags(&evJoin, cudaEventDisableTiming);

    cudaEventRecord(evFork, 0);
    cudaStreamWaitEvent(s2, evFork, 0);

    // --- chain B (s2): node projection + xh1 GEMM (independent of CSR) ---
    k_gemm_k128_m64<<<(n + 63) / 64, 256, G128_SMEM, s2>>>(x, Wp, bp, nullptr, nullptr, d_h0, n, 0);
    k_gemm_k64_m128<<<(n + 63) / 64, 256, G64_SMEM, s2>>>(d_h0, W1, as1, ad1, d_xh1, n);
    cudaEventRecord(evJoin, s2);

    // --- chain A (default): init + CSR build ---
    k_init <<<160, 256>>>(ei, n, G);
    k_hist <<<(et + 1023) / 1024, 256>>>(ei, e, et);
    k_scan <<<1, 1024>>>(n + 1);
    k_place<<<(et + 2047) / 2048, 256>>>(ei, e, et);

    // join: agg1 needs CSR + xh1 + as1/ad1
    cudaStreamWaitEvent(0, evJoin, 0);
    k_agg1<<<(n + 7) / 8, 256>>>(b1, n);
    k_gemm_k128_m64<<<(n + 63) / 64, 256, G128_SMEM>>>(d_out1, W2, nullptr, as2, ad2, d_xh2, n, 1);
    k_agg2<<<(n + 7) / 8, 256>>>(b2, batch, n);
    k_mlp<<<G, 64>>>(Wm1, bm1, Wm2, bm2, Wc, bc, Wr, br, Wv, bv, out, G);
}